// round 1
// baseline (speedup 1.0000x reference)
#include <cuda_runtime.h>
#include <math.h>

#define NB   16
#define SEQN 20
#define PP   1024
#define VD   256
#define HND  512
#define EMBD 300
#define CIN  776
#define DHD  128

// ---------------- scratch (device globals; no allocation) ----------------
__device__ float g_base [NB*PP*VD];   // step-invariant conv contribution (spatial+hn), layout (n,p,c)
__device__ float g_tpre [NB*PP*VD];   // relu(conv) pre-LN
__device__ float g_t    [NB*PP*VD];   // after mnorm LN
__device__ float g_kh   [NB*PP*VD];
__device__ float g_vv   [NB*PP*VD];
__device__ float g_o    [NB*PP*VD];
__device__ float g_fea1 [NB*PP*VD];
__device__ float g_featA[NB*VD*PP];   // NCHW ping
__device__ float g_featB[NB*VD*PP];   // NCHW pong
__device__ float g_wsum9[9*HND*VD];   // [type][i][o]
__device__ float g_hncon[NB*9*VD];    // [n][type][o]
__device__ float g_spbase[PP*VD];     // [p][o]
__device__ float g_qh   [SEQN*NB*VD]; // [s][n][c] : (relu(emb@qw^T+qb)) @ Wq^T + bq

// ---------------- precompute: hn-channel tap sums per border type ----------------
__global__ void k_wsum9(const float* __restrict__ w) {
    int idx = blockIdx.x*256 + threadIdx.x;
    if (idx >= 9*HND*VD) return;
    int o = idx & 255;
    int i = (idx >> 8) & 511;
    int t = idx >> 17;          // /(512*256)
    int ty = t/3, tx = t%3;
    int kh0 = (ty==0)?1:0, kh1 = (ty==2)?1:2;
    int kw0 = (tx==0)?1:0, kw1 = (tx==2)?1:2;
    const float* wb = w + ((size_t)o*CIN + 264 + i)*9;
    float s = 0.f;
    for (int kh=kh0; kh<=kh1; kh++)
        for (int kw=kw0; kw<=kw1; kw++)
            s += wb[kh*3+kw];
    g_wsum9[idx] = s;           // layout (t*512+i)*256+o == idx
}

__global__ void k_hncon(const float* __restrict__ hn) {
    int idx = blockIdx.x*256 + threadIdx.x;
    if (idx >= NB*9*VD) return;
    int o = idx & 255, t = (idx >> 8) % 9, n = idx / (9*256);
    const float* hp = hn + (size_t)n*HND;
    const float* wp = g_wsum9 + (size_t)t*HND*VD + o;
    float s = 0.f;
    for (int i=0;i<HND;i++) s += hp[i]*wp[(size_t)i*VD];
    g_hncon[idx] = s;
}

// ---------------- precompute: spatial-channel conv (per pixel, batch-invariant) ----------------
__global__ void k_spbase(const float* __restrict__ w) {
    int idx = blockIdx.x*256 + threadIdx.x;
    if (idx >= PP*VD) return;
    int o = idx & 255, p = idx >> 8;
    int hh = p >> 5, ww = p & 31;
    float s = 0.f;
    for (int kh=0;kh<3;kh++) {
        int gh = hh+kh-1; if ((unsigned)gh >= 32u) continue;
        for (int kw=0;kw<3;kw++) {
            int gw = ww+kw-1; if ((unsigned)gw >= 32u) continue;
            float xmin = gw*0.0625f - 1.f;
            float ymin = gh*0.0625f - 1.f;
            float xmax = xmin + 0.0625f;
            float ymax = ymin + 0.0625f;
            float f0=xmin, f1=ymin, f2=xmax, f3=ymax;
            float f4=(xmin+xmax)*0.5f, f5=(ymin+ymax)*0.5f;
            float f6=0.03125f, f7=0.03125f;
            const float* wb = w + ((size_t)o*CIN + 256)*9 + kh*3+kw;
            s += f0*wb[0*9] + f1*wb[1*9] + f2*wb[2*9] + f3*wb[3*9]
               + f4*wb[4*9] + f5*wb[5*9] + f6*wb[6*9] + f7*wb[7*9];
        }
    }
    g_spbase[idx] = s;
}

__global__ void k_assemble() {
    int idx = blockIdx.x*256 + threadIdx.x;
    if (idx >= NB*PP*VD/4) return;
    int e = idx*4;
    int o = e & 255, p = (e >> 8) & 1023, n = e >> 18;
    int hh = p >> 5, ww = p & 31;
    int ty = (hh==0)?0:((hh==31)?2:1);
    int tx = (ww==0)?0:((ww==31)?2:1);
    float4 sp = *(const float4*)(g_spbase + (size_t)p*VD + o);
    float4 hc = *(const float4*)(g_hncon + ((size_t)(n*9 + ty*3+tx))*VD + o);
    float4 r; r.x=sp.x+hc.x; r.y=sp.y+hc.y; r.z=sp.z+hc.z; r.w=sp.w+hc.w;
    *(float4*)(g_base + (size_t)e) = r;
}

// ---------------- precompute: q and qh for all steps (broadcast over P) ----------------
__global__ __launch_bounds__(256) void k_qh(const float* __restrict__ emb,
                                            const float* __restrict__ qw, const float* __restrict__ qb,
                                            const float* __restrict__ Wq, const float* __restrict__ bq) {
    __shared__ float es[304];
    __shared__ float qs[256];
    int n = blockIdx.x, s = blockIdx.y, c = threadIdx.x;
    for (int i=c; i<EMBD; i+=256) es[i] = emb[((size_t)n*SEQN+s)*EMBD + i];
    __syncthreads();
    float a = qb[c];
    const float* wr = qw + (size_t)c*EMBD;
    for (int e=0;e<EMBD;e++) a += es[e]*wr[e];
    qs[c] = fmaxf(a, 0.f);
    __syncthreads();
    float a2 = bq[c];
    const float* wr2 = Wq + (size_t)c*VD;
    for (int k=0;k<VD;k++) a2 += qs[k]*wr2[k];
    g_qh[((size_t)s*NB+n)*VD + c] = a2;
}

// ---------------- per-step: conv over the 256 feature channels (+base, relu) ----------------
__global__ __launch_bounds__(256) void k_conv(const float* __restrict__ fin,
                                              const float* __restrict__ wconv) {
    __shared__ float xs[4*1156];     // 4 ch x 34x34 halo tile
    __shared__ float ws[16*4*9];     // 16 oc x 4 ic x 9 taps
    int oc_base = blockIdx.x*16;
    int n = blockIdx.y;
    int tid = threadIdx.x;
    int col = tid & 31, r0 = tid >> 5;
    float acc[4][16];
#pragma unroll
    for (int i=0;i<4;i++)
#pragma unroll
        for (int j=0;j<16;j++) acc[i][j]=0.f;

    for (int ci0=0; ci0<256; ci0+=4) {
        __syncthreads();
        for (int idx=tid; idx<4*1156; idx+=256) {
            int ci = idx/1156, rr = idx - ci*1156;
            int r = rr/34, c = rr - r*34;
            int gh = r-1, gw = c-1;
            float v = 0.f;
            if ((unsigned)gh < 32u && (unsigned)gw < 32u)
                v = fin[(((size_t)n*256 + ci0+ci)<<10) + (gh<<5) + gw];
            xs[idx] = v;
        }
        for (int idx=tid; idx<576; idx+=256) {
            int oc = idx/36, rr = idx - oc*36;
            ws[idx] = wconv[(((size_t)(oc_base+oc))*CIN + ci0 + rr/9)*9 + rr%9];
        }
        __syncthreads();
#pragma unroll
        for (int ci=0; ci<4; ci++) {
#pragma unroll
            for (int tap=0; tap<9; tap++) {
                int kh = tap/3, kw = tap - kh*3;
                const float* xb = &xs[ci*1156 + (r0+kh)*34 + col + kw];
                float x0 = xb[0*8*34];
                float x1 = xb[1*8*34];
                float x2 = xb[2*8*34];
                float x3 = xb[3*8*34];
                const float* wb = &ws[ci*9 + tap];
#pragma unroll
                for (int oc=0; oc<16; oc++) {
                    float wv = wb[oc*36];
                    acc[0][oc] += wv*x0;
                    acc[1][oc] += wv*x1;
                    acc[2][oc] += wv*x2;
                    acc[3][oc] += wv*x3;
                }
            }
        }
    }
#pragma unroll
    for (int pos=0; pos<4; pos++) {
        int hrow = r0 + pos*8;
        size_t off = ((size_t)(n*PP + hrow*32 + col))*VD + oc_base;
        const float4* bp = (const float4*)(g_base + off);
        float4* op = (float4*)(g_tpre + off);
#pragma unroll
        for (int q=0;q<4;q++) {
            float4 b4 = bp[q];
            float4 v;
            v.x = fmaxf(acc[pos][q*4+0]+b4.x, 0.f);
            v.y = fmaxf(acc[pos][q*4+1]+b4.y, 0.f);
            v.z = fmaxf(acc[pos][q*4+2]+b4.z, 0.f);
            v.w = fmaxf(acc[pos][q*4+3]+b4.w, 0.f);
            op[q] = v;
        }
    }
}

// ---------------- per-step: LN of t_pre -> t (warp per row, two-pass) ----------------
__global__ __launch_bounds__(256) void k_ln(const float* __restrict__ g, const float* __restrict__ b) {
    int warp = threadIdx.x >> 5, lane = threadIdx.x & 31;
    int row = blockIdx.x*8 + warp;
    const float4* rp = (const float4*)(g_tpre + (size_t)row*VD);
    float4 a = rp[lane], c = rp[lane+32];
    float s = a.x+a.y+a.z+a.w + c.x+c.y+c.z+c.w;
#pragma unroll
    for (int o=16;o>=1;o>>=1) s += __shfl_xor_sync(0xffffffffu, s, o);
    float m = s * (1.f/256.f);
    float q = (a.x-m)*(a.x-m)+(a.y-m)*(a.y-m)+(a.z-m)*(a.z-m)+(a.w-m)*(a.w-m)
            + (c.x-m)*(c.x-m)+(c.y-m)*(c.y-m)+(c.z-m)*(c.z-m)+(c.w-m)*(c.w-m);
#pragma unroll
    for (int o=16;o>=1;o>>=1) q += __shfl_xor_sync(0xffffffffu, q, o);
    float rs = rsqrtf(q*(1.f/256.f) + 1e-5f);
    int c0 = lane*4, c1 = 128 + lane*4;
    float4 r1, r2;
    r1.x = (a.x-m)*rs*g[c0+0]+b[c0+0];
    r1.y = (a.y-m)*rs*g[c0+1]+b[c0+1];
    r1.z = (a.z-m)*rs*g[c0+2]+b[c0+2];
    r1.w = (a.w-m)*rs*g[c0+3]+b[c0+3];
    r2.x = (c.x-m)*rs*g[c1+0]+b[c1+0];
    r2.y = (c.y-m)*rs*g[c1+1]+b[c1+1];
    r2.z = (c.z-m)*rs*g[c1+2]+b[c1+2];
    r2.w = (c.w-m)*rs*g[c1+3]+b[c1+3];
    float4* op = (float4*)(g_t + (size_t)row*VD);
    op[lane] = r1; op[lane+32] = r2;
}

// ---------------- generic GEMM: C(16384x256) = A(16384x256) @ W^T(256x256), epilogues ----------------
// EPI 0: +bias      EPI 1: +bias,relu      EPI 2: +bias,+resid,LayerNorm(row)
template<int EPI>
__global__ __launch_bounds__(256) void k_gemm(const float* __restrict__ A, const float* __restrict__ W,
                                              const float* __restrict__ bias, const float* __restrict__ resid,
                                              const float* __restrict__ lng, const float* __restrict__ lnb,
                                              float* __restrict__ C) {
    __shared__ float As[64*17];
    __shared__ float Ws[16*257];
    int tid = threadIdx.x;
    int tx = tid & 15, ty = tid >> 4;
    int row0 = blockIdx.x*64;
    float acc[4][16];
#pragma unroll
    for (int i=0;i<4;i++)
#pragma unroll
        for (int j=0;j<16;j++) acc[i][j]=0.f;

    for (int k0=0;k0<256;k0+=16) {
        __syncthreads();
        {
            int r = tid >> 4, k = tid & 15;
#pragma unroll
            for (int it=0; it<4; it++)
                As[(r + it*16)*17 + k] = A[((size_t)(row0 + r + it*16))*256 + k0 + k];
#pragma unroll
            for (int it=0; it<16; it++) {
                int c = r + it*16;
                Ws[k*257 + c] = W[(size_t)c*256 + k0 + k];
            }
        }
        __syncthreads();
#pragma unroll
        for (int k=0;k<16;k++) {
            float a0 = As[(ty*4+0)*17+k];
            float a1 = As[(ty*4+1)*17+k];
            float a2 = As[(ty*4+2)*17+k];
            float a3 = As[(ty*4+3)*17+k];
#pragma unroll
            for (int j=0;j<16;j++) {
                float wv = Ws[k*257 + tx + j*16];
                acc[0][j] += a0*wv;
                acc[1][j] += a1*wv;
                acc[2][j] += a2*wv;
                acc[3][j] += a3*wv;
            }
        }
    }
#pragma unroll
    for (int i=0;i<4;i++) {
        int row = row0 + ty*4 + i;
        if (EPI == 2) {
            float v[16];
            float s = 0.f;
#pragma unroll
            for (int j=0;j<16;j++) {
                int c = tx + j*16;
                v[j] = acc[i][j] + bias[c] + resid[(size_t)row*256 + c];
                s += v[j];
            }
#pragma unroll
            for (int o=8;o>=1;o>>=1) s += __shfl_xor_sync(0xffffffffu, s, o, 16);
            float m = s*(1.f/256.f);
            float q = 0.f;
#pragma unroll
            for (int j=0;j<16;j++) { float d = v[j]-m; q += d*d; }
#pragma unroll
            for (int o=8;o>=1;o>>=1) q += __shfl_xor_sync(0xffffffffu, q, o, 16);
            float rs = rsqrtf(q*(1.f/256.f) + 1e-5f);
#pragma unroll
            for (int j=0;j<16;j++) {
                int c = tx + j*16;
                C[(size_t)row*256 + c] = (v[j]-m)*rs*lng[c] + lnb[c];
            }
        } else {
#pragma unroll
            for (int j=0;j<16;j++) {
                int c = tx + j*16;
                float v = acc[i][j] + bias[c];
                if (EPI == 1) v = fmaxf(v, 0.f);
                C[(size_t)row*256 + c] = v;
            }
        }
    }
}

// ---------------- per-step: attention, block per spatial position p (both heads) ----------------
__global__ __launch_bounds__(256) void k_attn(int s) {
    __shared__ float ks[16*257];
    __shared__ float vs[16*257];
    __shared__ float sc[512];       // [h][l][m]
    int p = blockIdx.x, tid = threadIdx.x;
    for (int idx=tid; idx<16*256; idx+=256) {
        int m = idx >> 8, c = idx & 255;
        ks[m*257+c] = g_kh[((size_t)(m*PP + p))*VD + c];
        vs[m*257+c] = g_vv[((size_t)(m*PP + p))*VD + c];
    }
    __syncthreads();
    const float scale = 0.08838834764831845f;  // 1/sqrt(128)
#pragma unroll
    for (int rep=0; rep<2; rep++) {
        int si = tid + rep*256;
        int h = si >> 8, l = (si >> 4) & 15, m = si & 15;
        const float* qp = g_qh + ((size_t)(s*NB + l))*VD + h*DHD;
        const float* kp = ks + m*257 + h*DHD;
        float d = 0.f;
#pragma unroll 8
        for (int k=0;k<DHD;k++) d += qp[k]*kp[k];
        sc[si] = d*scale;
    }
    __syncthreads();
    if (tid < 32) {
        float* r = sc + tid*16;
        float mx = r[0];
#pragma unroll
        for (int m=1;m<16;m++) mx = fmaxf(mx, r[m]);
        float sum=0.f;
#pragma unroll
        for (int m=0;m<16;m++){ float e = __expf(r[m]-mx); r[m]=e; sum+=e; }
        float inv = 1.f/sum;
#pragma unroll
        for (int m=0;m<16;m++) r[m]*=inv;
    }
    __syncthreads();
    for (int idx=tid; idx<4096; idx+=256) {
        int l = idx >> 8, c = idx & 255;
        int h = c >> 7;
        const float* a = sc + (h*16+l)*16;
        float accv = 0.f;
#pragma unroll
        for (int m=0;m<16;m++) accv += a[m]*vs[m*257+c];
        g_o[((size_t)(l*PP+p))*VD + c] = accv;
    }
}

// ---------------- per-step: gated transpose back to NCHW ----------------
__global__ __launch_bounds__(256) void k_write(const float* __restrict__ fea, const float* __restrict__ fcur,
                                               float* __restrict__ fnext, const int* __restrict__ words, int s) {
    __shared__ float tile[32][33];
    int n = blockIdx.z, p0 = blockIdx.y*32, c0 = blockIdx.x*32;
    int tid = threadIdx.x;
    int active = (words[s] != 0);
    if (active) {
        for (int l=tid; l<1024; l+=256) {
            int i = l>>5, j = l&31;
            tile[i][j] = fea[((size_t)(n*PP + p0+i))*VD + c0+j];
        }
        __syncthreads();
        for (int l=tid; l<1024; l+=256) {
            int i = l>>5, j = l&31;
            fnext[((size_t)(n*VD + c0+i))*PP + p0+j] = tile[j][i];
        }
    } else {
        for (int l=tid; l<1024; l+=256) {
            int i = l>>5, j = l&31;
            size_t off = ((size_t)(n*VD + c0+i))*PP + p0+j;
            fnext[off] = fcur[off];
        }
    }
}

// ---------------- launch ----------------
extern "C" void kernel_launch(void* const* d_in, const int* in_sizes, int n_in,
                              void* d_out, int out_size) {
    const float* hn         = (const float*)d_in[1];
    const float* feature    = (const float*)d_in[2];
    const float* embedding  = (const float*)d_in[3];
    const int*   words      = (const int*)  d_in[4];
    const float* qconv_w    = (const float*)d_in[5];
    const float* qconv_b    = (const float*)d_in[6];
    const float* mconv_w    = (const float*)d_in[7];
    const float* mnorm_g    = (const float*)d_in[8];
    const float* mnorm_b    = (const float*)d_in[9];
    const float* in_proj_w  = (const float*)d_in[10];
    const float* in_proj_b  = (const float*)d_in[11];
    const float* out_proj_w = (const float*)d_in[12];
    const float* out_proj_b = (const float*)d_in[13];
    const float* norm_g     = (const float*)d_in[14];
    const float* norm_b     = (const float*)d_in[15];
    const float* lin1_w     = (const float*)d_in[16];
    const float* lin1_b     = (const float*)d_in[17];
    const float* lin2_w     = (const float*)d_in[18];
    const float* lin2_b     = (const float*)d_in[19];
    const float* normf_g    = (const float*)d_in[20];
    const float* normf_b    = (const float*)d_in[21];

    float *fA, *fB, *p_t, *p_kh, *p_vv, *p_o, *p_fea1;
    cudaGetSymbolAddress((void**)&fA,     g_featA);
    cudaGetSymbolAddress((void**)&fB,     g_featB);
    cudaGetSymbolAddress((void**)&p_t,    g_t);
    cudaGetSymbolAddress((void**)&p_kh,   g_kh);
    cudaGetSymbolAddress((void**)&p_vv,   g_vv);
    cudaGetSymbolAddress((void**)&p_o,    g_o);
    cudaGetSymbolAddress((void**)&p_fea1, g_fea1);

    // step-invariant precompute
    k_wsum9  <<<(9*HND*VD+255)/256, 256>>>(mconv_w);
    k_spbase <<<(PP*VD+255)/256,    256>>>(mconv_w);
    k_hncon  <<<(NB*9*VD+255)/256,  256>>>(hn);
    k_assemble<<<(NB*PP*VD/4+255)/256, 256>>>();
    k_qh     <<<dim3(NB,SEQN), 256>>>(embedding, qconv_w, qconv_b, in_proj_w, in_proj_b);

    for (int s=0; s<SEQN; s++) {
        const float* fin = (s==0) ? feature : ((s&1) ? fA : fB);
        float* fout = (s==SEQN-1) ? (float*)d_out : ((s&1) ? fB : fA);

        k_conv<<<dim3(16,16), 256>>>(fin, mconv_w);
        k_ln  <<<NB*PP/8, 256>>>(mnorm_g, mnorm_b);
        k_gemm<0><<<256,256>>>(p_t, in_proj_w + VD*VD,   in_proj_b + VD,   nullptr, nullptr, nullptr, p_kh);
        k_gemm<0><<<256,256>>>(p_t, in_proj_w + 2*VD*VD, in_proj_b + 2*VD, nullptr, nullptr, nullptr, p_vv);
        k_attn<<<PP, 256>>>(s);
        k_gemm<2><<<256,256>>>(p_o,    out_proj_w, out_proj_b, p_t,    norm_g,  norm_b,  p_fea1);
        k_gemm<1><<<256,256>>>(p_fea1, lin1_w,     lin1_b,     nullptr, nullptr, nullptr, p_kh);
        k_gemm<2><<<256,256>>>(p_kh,   lin2_w,     lin2_b,     p_fea1, normf_g, normf_b, p_vv);
        k_write<<<dim3(8,32,NB), 256>>>(p_vv, fin, fout, words, s);
    }
}

// round 3
// speedup vs baseline: 2.2406x; 2.2406x over previous
#include <cuda_runtime.h>
#include <math.h>
#include <stdint.h>

#define NB   16
#define SEQN 20
#define PP   1024
#define VD   256
#define HND  512
#define EMBD 300
#define CIN  776
#define DHD  128

#define ASZ (128*33)
#define BSZ (256*33)
#define SMEM_BYTES ((2*ASZ + 2*BSZ)*4)

// ---------------- scratch (device globals; no allocation) ----------------
__device__ float g_base [NB*PP*VD];
__device__ float g_t    [NB*PP*VD];
__device__ float g_kh   [NB*PP*VD];
__device__ float g_vv   [NB*PP*VD];
__device__ float g_o    [NB*PP*VD];
__device__ float g_fea1 [NB*PP*VD];
__device__ float g_featA[NB*PP*VD];   // NHWC ping
__device__ float g_featB[NB*PP*VD];   // NHWC pong
__device__ float g_wsum9[9*HND*VD];
__device__ float g_hncon[NB*9*VD];
__device__ float g_spbase[PP*VD];
__device__ float g_qh   [SEQN*NB*VD];
__device__ float g_wr   [9*VD*VD];    // [tap][oc][ic]

// ---------------- helpers ----------------
__device__ __forceinline__ float tf32r(float x){
    uint32_t r; asm("cvt.rna.tf32.f32 %0, %1;" : "=r"(r) : "f"(x));
    return __uint_as_float(r);
}
__device__ __forceinline__ void mma8(float* d, const uint32_t* a, const uint32_t* b){
    asm volatile("mma.sync.aligned.m16n8k8.row.col.f32.tf32.tf32.f32 "
        "{%0,%1,%2,%3}, {%4,%5,%6,%7}, {%8,%9}, {%0,%1,%2,%3};"
        : "+f"(d[0]), "+f"(d[1]), "+f"(d[2]), "+f"(d[3])
        : "r"(a[0]), "r"(a[1]), "r"(a[2]), "r"(a[3]), "r"(b[0]), "r"(b[1]));
}

// ---------------- precompute kernels (validated in R1) ----------------
__global__ void k_wsum9(const float* __restrict__ w) {
    int idx = blockIdx.x*256 + threadIdx.x;
    if (idx >= 9*HND*VD) return;
    int o = idx & 255;
    int i = (idx >> 8) & 511;
    int t = idx >> 17;
    int ty = t/3, tx = t%3;
    int kh0 = (ty==0)?1:0, kh1 = (ty==2)?1:2;
    int kw0 = (tx==0)?1:0, kw1 = (tx==2)?1:2;
    const float* wb = w + ((size_t)o*CIN + 264 + i)*9;
    float s = 0.f;
    for (int kh=kh0; kh<=kh1; kh++)
        for (int kw=kw0; kw<=kw1; kw++)
            s += wb[kh*3+kw];
    g_wsum9[idx] = s;
}

__global__ void k_hncon(const float* __restrict__ hn) {
    int idx = blockIdx.x*256 + threadIdx.x;
    if (idx >= NB*9*VD) return;
    int o = idx & 255, t = (idx >> 8) % 9, n = idx / (9*256);
    const float* hp = hn + (size_t)n*HND;
    const float* wp = g_wsum9 + (size_t)t*HND*VD + o;
    float s = 0.f;
    for (int i=0;i<HND;i++) s += hp[i]*wp[(size_t)i*VD];
    g_hncon[idx] = s;
}

__global__ void k_spbase(const float* __restrict__ w) {
    int idx = blockIdx.x*256 + threadIdx.x;
    if (idx >= PP*VD) return;
    int o = idx & 255, p = idx >> 8;
    int hh = p >> 5, ww = p & 31;
    float s = 0.f;
    for (int kh=0;kh<3;kh++) {
        int gh = hh+kh-1; if ((unsigned)gh >= 32u) continue;
        for (int kw=0;kw<3;kw++) {
            int gw = ww+kw-1; if ((unsigned)gw >= 32u) continue;
            float xmin = gw*0.0625f - 1.f;
            float ymin = gh*0.0625f - 1.f;
            float xmax = xmin + 0.0625f;
            float ymax = ymin + 0.0625f;
            const float* wb = w + ((size_t)o*CIN + 256)*9 + kh*3+kw;
            s += xmin*wb[0*9] + ymin*wb[1*9] + xmax*wb[2*9] + ymax*wb[3*9]
               + 0.5f*(xmin+xmax)*wb[4*9] + 0.5f*(ymin+ymax)*wb[5*9]
               + 0.03125f*wb[6*9] + 0.03125f*wb[7*9];
        }
    }
    g_spbase[idx] = s;
}

__global__ void k_assemble() {
    int idx = blockIdx.x*256 + threadIdx.x;
    if (idx >= NB*PP*VD/4) return;
    int e = idx*4;
    int o = e & 255, p = (e >> 8) & 1023, n = e >> 18;
    int hh = p >> 5, ww = p & 31;
    int ty = (hh==0)?0:((hh==31)?2:1);
    int tx = (ww==0)?0:((ww==31)?2:1);
    float4 sp = *(const float4*)(g_spbase + (size_t)p*VD + o);
    float4 hc = *(const float4*)(g_hncon + ((size_t)(n*9 + ty*3+tx))*VD + o);
    float4 r; r.x=sp.x+hc.x; r.y=sp.y+hc.y; r.z=sp.z+hc.z; r.w=sp.w+hc.w;
    *(float4*)(g_base + (size_t)e) = r;
}

__global__ __launch_bounds__(256) void k_qh(const float* __restrict__ emb,
                                            const float* __restrict__ qw, const float* __restrict__ qb,
                                            const float* __restrict__ Wq, const float* __restrict__ bq) {
    __shared__ float es[304];
    __shared__ float qs[256];
    int n = blockIdx.x, s = blockIdx.y, c = threadIdx.x;
    for (int i=c; i<EMBD; i+=256) es[i] = emb[((size_t)n*SEQN+s)*EMBD + i];
    __syncthreads();
    float a = qb[c];
    const float* wr = qw + (size_t)c*EMBD;
    for (int e=0;e<EMBD;e++) a += es[e]*wr[e];
    qs[c] = fmaxf(a, 0.f);
    __syncthreads();
    float a2 = bq[c];
    const float* wr2 = Wq + (size_t)c*VD;
    for (int k=0;k<VD;k++) a2 += qs[k]*wr2[k];
    g_qh[((size_t)s*NB+n)*VD + c] = a2;
}

__global__ void k_repack(const float* __restrict__ w){
    int idx = blockIdx.x*256 + threadIdx.x;
    if (idx >= 9*VD*VD) return;
    int i = idx & 255;
    int o = (idx >> 8) & 255;
    int t = idx >> 16;
    g_wr[idx] = w[((size_t)o*CIN + i)*9 + t];
}

// ---------------- transposes (once each) ----------------
__global__ __launch_bounds__(256) void k_tr_in(const float* __restrict__ src, float* __restrict__ dst){
    __shared__ float t[32][33];
    int n = blockIdx.z, c0 = blockIdx.y*32, p0 = blockIdx.x*32;
    int i = threadIdx.x >> 5, j = threadIdx.x & 31;
    for (int r=0;r<32;r+=8)
        t[i+r][j] = src[((size_t)n*VD + c0+i+r)*PP + p0 + j];
    __syncthreads();
    for (int r=0;r<32;r+=8)
        dst[((size_t)n*PP + p0+i+r)*VD + c0 + j] = t[j][i+r];
}
__global__ __launch_bounds__(256) void k_tr_out(const float* __restrict__ src, float* __restrict__ dst){
    __shared__ float t[32][33];
    int n = blockIdx.z, c0 = blockIdx.y*32, p0 = blockIdx.x*32;
    int i = threadIdx.x >> 5, j = threadIdx.x & 31;
    for (int r=0;r<32;r+=8)
        t[i+r][j] = src[((size_t)n*PP + p0+i+r)*VD + c0 + j];
    __syncthreads();
    for (int r=0;r<32;r+=8)
        dst[((size_t)n*VD + c0+i+r)*PP + p0 + j] = t[j][i+r];
}

// ---------------- tf32 HMMA GEMM: C(16384x256) = A @ W^T (+fused epilogues) -------
// MODE 0: plain GEMM, K=256.   MODE 1: conv (9 shifted taps), W=g_wr, resid=base.
// EPI 0: +bias   EPI 1: +bias,relu   EPI 2: +bias,+resid,LN
// EPI 3: EPI2 + word-gate (copy fcur when inactive)   EPI 4: LN(relu(acc+resid)) (conv)
template<int MODE, int EPI>
__global__ __launch_bounds__(512, 1) void k_tc(const float* __restrict__ A, const float* __restrict__ W,
    const float* __restrict__ bias, const float* __restrict__ resid,
    const float* __restrict__ lng, const float* __restrict__ lnb,
    const int* __restrict__ words, int s, const float* __restrict__ fcur,
    float* __restrict__ C)
{
    extern __shared__ float sm[];
    const int tid  = threadIdx.x;
    const int lane = tid & 31;
    const int w    = tid >> 5;
    const int wm   = w & 3;
    const int wn   = w >> 2;
    const int tg   = lane & 3;
    const int gp   = lane >> 2;
    const int row0 = blockIdx.x*128;
    const int n    = row0 >> 10;
    const int p0   = row0 & 1023;

    float acc[2][8][4];
#pragma unroll
    for (int f=0;f<2;f++)
#pragma unroll
        for (int nf=0;nf<8;nf++)
#pragma unroll
            for (int j=0;j<4;j++) acc[f][nf][j] = 0.f;

    const int CH = MODE ? 72 : 8;

    auto ldgA = [&](int c, float4* r){
#pragma unroll
        for (int i=0;i<2;i++){
            int q = tid + i*512;
            int row = q>>3, c4 = q&7;
            if (MODE == 0){
                r[i] = *(const float4*)(A + (size_t)(row0+row)*256 + c*32 + c4*4);
            } else {
                int tap = c >> 3, kb = c & 7;
                int dh = tap/3 - 1, dw = tap%3 - 1;
                int p = p0 + row;
                int sh = (p>>5) + dh, sw = (p&31) + dw;
                float4 v = make_float4(0.f,0.f,0.f,0.f);
                if ((unsigned)sh < 32u && (unsigned)sw < 32u)
                    v = *(const float4*)(A + ((size_t)((n<<10) + (sh<<5) + sw))*256 + kb*32 + c4*4);
                r[i] = v;
            }
        }
    };
    auto ldgB = [&](int c, float4* r){
        const float* Wb; int k0;
        if (MODE == 0){ Wb = W; k0 = c*32; }
        else { Wb = g_wr + (size_t)(c>>3)*VD*VD; k0 = (c&7)*32; }
#pragma unroll
        for (int i=0;i<4;i++){
            int q = tid + i*512;
            int row = q>>3, c4 = q&7;
            r[i] = *(const float4*)(Wb + (size_t)row*256 + k0 + c4*4);
        }
    };
    auto stsA = [&](int buf, const float4* r){
        float* As = sm + buf*ASZ;
#pragma unroll
        for (int i=0;i<2;i++){
            int q = tid + i*512;
            int row = q>>3, c4 = q&7;
            float* p = As + row*33 + c4*4;
            p[0]=tf32r(r[i].x); p[1]=tf32r(r[i].y); p[2]=tf32r(r[i].z); p[3]=tf32r(r[i].w);
        }
    };
    auto stsB = [&](int buf, const float4* r){
        float* Bs = sm + 2*ASZ + buf*BSZ;
#pragma unroll
        for (int i=0;i<4;i++){
            int q = tid + i*512;
            int row = q>>3, c4 = q&7;
            float* p = Bs + row*33 + c4*4;
            p[0]=tf32r(r[i].x); p[1]=tf32r(r[i].y); p[2]=tf32r(r[i].z); p[3]=tf32r(r[i].w);
        }
    };
    auto compute = [&](int buf){
        const float* As = sm + buf*ASZ;
        const float* Bs = sm + 2*ASZ + buf*BSZ;
#pragma unroll
        for (int kk=0; kk<4; kk++){
            int k = kk*8;
            uint32_t af[2][4];
#pragma unroll
            for (int f=0;f<2;f++){
                int rb = wm*32 + f*16 + gp;
                af[f][0] = __float_as_uint(As[rb*33     + k + tg]);
                af[f][1] = __float_as_uint(As[(rb+8)*33 + k + tg]);
                af[f][2] = __float_as_uint(As[rb*33     + k + tg + 4]);
                af[f][3] = __float_as_uint(As[(rb+8)*33 + k + tg + 4]);
            }
#pragma unroll
            for (int nf=0;nf<8;nf++){
                int cb = wn*64 + nf*8 + gp;
                uint32_t bf[2];
                bf[0] = __float_as_uint(Bs[cb*33 + k + tg]);
                bf[1] = __float_as_uint(Bs[cb*33 + k + tg + 4]);
                mma8(acc[0][nf], af[0], bf);
                mma8(acc[1][nf], af[1], bf);
            }
        }
    };

    {
        float4 ra[2], rb[4];
        ldgA(0, ra); ldgB(0, rb);
        stsA(0, ra); stsB(0, rb);
    }
    __syncthreads();
    for (int c=0; c<CH; c++){
        float4 ra[2], rb[4];
        if (c+1 < CH){ ldgA(c+1, ra); ldgB(c+1, rb); }
        compute(c&1);
        __syncthreads();
        if (c+1 < CH){
            stsA((c+1)&1, ra); stsB((c+1)&1, rb);
            __syncthreads();
        }
    }

    // -------- epilogue --------
    if (EPI <= 1){
#pragma unroll
        for (int f=0;f<2;f++)
#pragma unroll
        for (int nf=0;nf<8;nf++){
            int colb = wn*64 + nf*8 + 2*tg;
            float2 bb = *(const float2*)(bias + colb);
#pragma unroll
            for (int h=0;h<2;h++){
                int row = row0 + wm*32 + f*16 + h*8 + gp;
                float2 o;
                o.x = acc[f][nf][2*h+0] + bb.x;
                o.y = acc[f][nf][2*h+1] + bb.y;
                if (EPI == 1){ o.x = fmaxf(o.x,0.f); o.y = fmaxf(o.y,0.f); }
                *(float2*)(C + (size_t)row*256 + colb) = o;
            }
        }
        return;
    }

    if (EPI == 3){
        if (__ldg(words + s) == 0){
#pragma unroll
            for (int f=0;f<2;f++)
#pragma unroll
            for (int nf=0;nf<8;nf++){
                int colb = wn*64 + nf*8 + 2*tg;
#pragma unroll
                for (int h=0;h<2;h++){
                    int row = row0 + wm*32 + f*16 + h*8 + gp;
                    *(float2*)(C + (size_t)row*256 + colb) =
                        *(const float2*)(fcur + (size_t)row*256 + colb);
                }
            }
            return;
        }
    }

#pragma unroll
    for (int f=0;f<2;f++)
#pragma unroll
    for (int nf=0;nf<8;nf++){
        int colb = wn*64 + nf*8 + 2*tg;
        float2 bb = make_float2(0.f, 0.f);
        if (EPI != 4) bb = *(const float2*)(bias + colb);
#pragma unroll
        for (int h=0;h<2;h++){
            int row = row0 + wm*32 + f*16 + h*8 + gp;
            float2 rr = *(const float2*)(resid + (size_t)row*256 + colb);
            float vx = acc[f][nf][2*h+0] + bb.x + rr.x;
            float vy = acc[f][nf][2*h+1] + bb.y + rr.y;
            if (EPI == 4){ vx = fmaxf(vx, 0.f); vy = fmaxf(vy, 0.f); }
            acc[f][nf][2*h+0] = vx;
            acc[f][nf][2*h+1] = vy;
        }
    }
    float2* red = (float2*)sm;   // reuse SMEM: [wn][128]
#pragma unroll
    for (int f=0;f<2;f++)
#pragma unroll
    for (int h=0;h<2;h++){
        float su = 0.f, sq = 0.f;
#pragma unroll
        for (int nf=0;nf<8;nf++){
            float vx = acc[f][nf][2*h+0], vy = acc[f][nf][2*h+1];
            su += vx + vy;
            sq += vx*vx + vy*vy;
        }
        su += __shfl_xor_sync(0xffffffffu, su, 1);
        sq += __shfl_xor_sync(0xffffffffu, sq, 1);
        su += __shfl_xor_sync(0xffffffffu, su, 2);
        sq += __shfl_xor_sync(0xffffffffu, sq, 2);
        if (tg == 0){
            int rloc = wm*32 + f*16 + h*8 + gp;
            red[wn*128 + rloc] = make_float2(su, sq);
        }
    }
    __syncthreads();
#pragma unroll
    for (int f=0;f<2;f++)
#pragma unroll
    for (int h=0;h<2;h++){
        int rloc = wm*32 + f*16 + h*8 + gp;
        float S = 0.f, Q = 0.f;
#pragma unroll
        for (int w4=0;w4<4;w4++){
            float2 v = red[w4*128 + rloc];
            S += v.x; Q += v.y;
        }
        float m  = S*(1.f/256.f);
        float rs = rsqrtf(Q*(1.f/256.f) - m*m + 1e-5f);
        int row = row0 + rloc;
#pragma unroll
        for (int nf=0;nf<8;nf++){
            int colb = wn*64 + nf*8 + 2*tg;
            float2 g2 = *(const float2*)(lng + colb);
            float2 b2 = *(const float2*)(lnb + colb);
            float2 o;
            o.x = (acc[f][nf][2*h+0]-m)*rs*g2.x + b2.x;
            o.y = (acc[f][nf][2*h+1]-m)*rs*g2.y + b2.y;
            *(float2*)(C + (size_t)row*256 + colb) = o;
        }
    }
}

// ---------------- attention (validated in R1) ----------------
__global__ __launch_bounds__(256) void k_attn(int s) {
    __shared__ float ks[16*257];
    __shared__ float vs[16*257];
    __shared__ float sc[512];
    int p = blockIdx.x, tid = threadIdx.x;
    for (int idx=tid; idx<16*256; idx+=256) {
        int m = idx >> 8, c = idx & 255;
        ks[m*257+c] = g_kh[((size_t)(m*PP + p))*VD + c];
        vs[m*257+c] = g_vv[((size_t)(m*PP + p))*VD + c];
    }
    __syncthreads();
    const float scale = 0.08838834764831845f;
#pragma unroll
    for (int rep=0; rep<2; rep++) {
        int si = tid + rep*256;
        int h = si >> 8, l = (si >> 4) & 15, m = si & 15;
        const float* qp = g_qh + ((size_t)(s*NB + l))*VD + h*DHD;
        const float* kp = ks + m*257 + h*DHD;
        float d = 0.f;
#pragma unroll 8
        for (int k=0;k<DHD;k++) d += qp[k]*kp[k];
        sc[si] = d*scale;
    }
    __syncthreads();
    if (tid < 32) {
        float* r = sc + tid*16;
        float mx = r[0];
#pragma unroll
        for (int m=1;m<16;m++) mx = fmaxf(mx, r[m]);
        float su=0.f;
#pragma unroll
        for (int m=0;m<16;m++){ float e = __expf(r[m]-mx); r[m]=e; su+=e; }
        float inv = 1.f/su;
#pragma unroll
        for (int m=0;m<16;m++) r[m]*=inv;
    }
    __syncthreads();
    for (int idx=tid; idx<4096; idx+=256) {
        int l = idx >> 8, c = idx & 255;
        int h = c >> 7;
        const float* a = sc + (h*16+l)*16;
        float accv = 0.f;
#pragma unroll
        for (int m=0;m<16;m++) accv += a[m]*vs[m*257+c];
        g_o[((size_t)(l*PP+p))*VD + c] = accv;
    }
}

// ---------------- launch ----------------
extern "C" void kernel_launch(void* const* d_in, const int* in_sizes, int n_in,
                              void* d_out, int out_size) {
    const float* hn         = (const float*)d_in[1];
    const float* feature    = (const float*)d_in[2];
    const float* embedding  = (const float*)d_in[3];
    const int*   words      = (const int*)  d_in[4];
    const float* qconv_w    = (const float*)d_in[5];
    const float* qconv_b    = (const float*)d_in[6];
    const float* mconv_w    = (const float*)d_in[7];
    const float* mnorm_g    = (const float*)d_in[8];
    const float* mnorm_b    = (const float*)d_in[9];
    const float* in_proj_w  = (const float*)d_in[10];
    const float* in_proj_b  = (const float*)d_in[11];
    const float* out_proj_w = (const float*)d_in[12];
    const float* out_proj_b = (const float*)d_in[13];
    const float* norm_g     = (const float*)d_in[14];
    const float* norm_b     = (const float*)d_in[15];
    const float* lin1_w     = (const float*)d_in[16];
    const float* lin1_b     = (const float*)d_in[17];
    const float* lin2_w     = (const float*)d_in[18];
    const float* lin2_b     = (const float*)d_in[19];
    const float* normf_g    = (const float*)d_in[20];
    const float* normf_b    = (const float*)d_in[21];

    cudaFuncSetAttribute(k_tc<0,0>, cudaFuncAttributeMaxDynamicSharedMemorySize, SMEM_BYTES);
    cudaFuncSetAttribute(k_tc<0,1>, cudaFuncAttributeMaxDynamicSharedMemorySize, SMEM_BYTES);
    cudaFuncSetAttribute(k_tc<0,2>, cudaFuncAttributeMaxDynamicSharedMemorySize, SMEM_BYTES);
    cudaFuncSetAttribute(k_tc<0,3>, cudaFuncAttributeMaxDynamicSharedMemorySize, SMEM_BYTES);
    cudaFuncSetAttribute(k_tc<1,4>, cudaFuncAttributeMaxDynamicSharedMemorySize, SMEM_BYTES);

    float *fA, *fB, *p_t, *p_kh, *p_vv, *p_o, *p_fea1, *p_base;
    cudaGetSymbolAddress((void**)&fA,     g_featA);
    cudaGetSymbolAddress((void**)&fB,     g_featB);
    cudaGetSymbolAddress((void**)&p_t,    g_t);
    cudaGetSymbolAddress((void**)&p_kh,   g_kh);
    cudaGetSymbolAddress((void**)&p_vv,   g_vv);
    cudaGetSymbolAddress((void**)&p_o,    g_o);
    cudaGetSymbolAddress((void**)&p_fea1, g_fea1);
    cudaGetSymbolAddress((void**)&p_base, g_base);

    // one-time precompute
    k_wsum9   <<<(9*HND*VD+255)/256, 256>>>(mconv_w);
    k_spbase  <<<(PP*VD+255)/256,    256>>>(mconv_w);
    k_hncon   <<<(NB*9*VD+255)/256,  256>>>(hn);
    k_assemble<<<(NB*PP*VD/4+255)/256, 256>>>();
    k_qh      <<<dim3(NB,SEQN), 256>>>(embedding, qconv_w, qconv_b, in_proj_w, in_proj_b);
    k_repack  <<<(9*VD*VD+255)/256,  256>>>(mconv_w);
    k_tr_in   <<<dim3(32,8,NB), 256>>>(feature, fA);

    for (int s=0; s<SEQN; s++) {
        const float* fin = (s&1) ? fB : fA;
        float* fout      = (s&1) ? fA : fB;

        // conv: LN(relu(conv + base)) -> g_t
        k_tc<1,4><<<128,512,SMEM_BYTES>>>(fin, nullptr, nullptr, p_base,
                                          mnorm_g, mnorm_b, nullptr, 0, nullptr, p_t);
        k_tc<0,0><<<128,512,SMEM_BYTES>>>(p_t, in_proj_w + VD*VD,   in_proj_b + VD,
                                          nullptr, nullptr, nullptr, nullptr, 0, nullptr, p_kh);
        k_tc<0,0><<<128,512,SMEM_BYTES>>>(p_t, in_proj_w + 2*VD*VD, in_proj_b + 2*VD,
                                          nullptr, nullptr, nullptr, nullptr, 0, nullptr, p_vv);
        k_attn <<<PP,256>>>(s);
        k_tc<0,2><<<128,512,SMEM_BYTES>>>(p_o, out_proj_w, out_proj_b,
                                          p_t, norm_g, norm_b, nullptr, 0, nullptr, p_fea1);
        k_tc<0,1><<<128,512,SMEM_BYTES>>>(p_fea1, lin1_w, lin1_b,
                                          nullptr, nullptr, nullptr, nullptr, 0, nullptr, p_kh);
        k_tc<0,3><<<128,512,SMEM_BYTES>>>(p_kh, lin2_w, lin2_b,
                                          p_fea1, normf_g, normf_b, words, s, fin, fout);
    }
    k_tr_out<<<dim3(32,8,NB), 256>>>(fA, (float*)d_out);
}

// round 4
// speedup vs baseline: 3.8417x; 1.7146x over previous
#include <cuda_runtime.h>
#include <math.h>
#include <stdint.h>

#define NB   16
#define SEQN 20
#define PP   1024
#define VD   256
#define HND  512
#define EMBD 300
#define CIN  776
#define DHD  128

#define PAD  36
#define ASZ (128*PAD)
#define BSZ (256*PAD)
#define SMEM_BYTES ((2*ASZ + 2*BSZ)*4)

// ---------------- scratch (device globals; no allocation) ----------------
__device__ float g_base [NB*PP*VD];
__device__ float g_t    [NB*PP*VD];
__device__ float g_kh   [NB*PP*VD];
__device__ float g_vv   [NB*PP*VD];
__device__ float g_o    [NB*PP*VD];
__device__ float g_fea1 [NB*PP*VD];
__device__ float g_featA[NB*PP*VD];   // NHWC ping
__device__ float g_featB[NB*PP*VD];   // NHWC pong
__device__ float g_wsum9[9*HND*VD];
__device__ float g_hncon[NB*9*VD];
__device__ float g_spbase[PP*VD];
__device__ float g_qh   [SEQN*NB*VD];
__device__ float g_wr   [9*VD*VD];    // [tap][oc][ic]

// ---------------- helpers ----------------
__device__ __forceinline__ float tf32r(float x){
    uint32_t r; asm("cvt.rna.tf32.f32 %0, %1;" : "=r"(r) : "f"(x));
    return __uint_as_float(r);
}
__device__ __forceinline__ void mma8(float* d, const uint32_t* a, const uint32_t* b){
    asm volatile("mma.sync.aligned.m16n8k8.row.col.f32.tf32.tf32.f32 "
        "{%0,%1,%2,%3}, {%4,%5,%6,%7}, {%8,%9}, {%0,%1,%2,%3};"
        : "+f"(d[0]), "+f"(d[1]), "+f"(d[2]), "+f"(d[3])
        : "r"(a[0]), "r"(a[1]), "r"(a[2]), "r"(a[3]), "r"(b[0]), "r"(b[1]));
}

// ---------------- precompute kernels (validated) ----------------
__global__ void k_wsum9(const float* __restrict__ w) {
    int idx = blockIdx.x*256 + threadIdx.x;
    if (idx >= 9*HND*VD) return;
    int o = idx & 255;
    int i = (idx >> 8) & 511;
    int t = idx >> 17;
    int ty = t/3, tx = t%3;
    int kh0 = (ty==0)?1:0, kh1 = (ty==2)?1:2;
    int kw0 = (tx==0)?1:0, kw1 = (tx==2)?1:2;
    const float* wb = w + ((size_t)o*CIN + 264 + i)*9;
    float s = 0.f;
    for (int kh=kh0; kh<=kh1; kh++)
        for (int kw=kw0; kw<=kw1; kw++)
            s += wb[kh*3+kw];
    g_wsum9[idx] = s;
}

__global__ void k_hncon(const float* __restrict__ hn) {
    int idx = blockIdx.x*256 + threadIdx.x;
    if (idx >= NB*9*VD) return;
    int o = idx & 255, t = (idx >> 8) % 9, n = idx / (9*256);
    const float* hp = hn + (size_t)n*HND;
    const float* wp = g_wsum9 + (size_t)t*HND*VD + o;
    float s = 0.f;
    for (int i=0;i<HND;i++) s += hp[i]*wp[(size_t)i*VD];
    g_hncon[idx] = s;
}

__global__ void k_spbase(const float* __restrict__ w) {
    int idx = blockIdx.x*256 + threadIdx.x;
    if (idx >= PP*VD) return;
    int o = idx & 255, p = idx >> 8;
    int hh = p >> 5, ww = p & 31;
    float s = 0.f;
    for (int kh=0;kh<3;kh++) {
        int gh = hh+kh-1; if ((unsigned)gh >= 32u) continue;
        for (int kw=0;kw<3;kw++) {
            int gw = ww+kw-1; if ((unsigned)gw >= 32u) continue;
            float xmin = gw*0.0625f - 1.f;
            float ymin = gh*0.0625f - 1.f;
            float xmax = xmin + 0.0625f;
            float ymax = ymin + 0.0625f;
            const float* wb = w + ((size_t)o*CIN + 256)*9 + kh*3+kw;
            s += xmin*wb[0*9] + ymin*wb[1*9] + xmax*wb[2*9] + ymax*wb[3*9]
               + 0.5f*(xmin+xmax)*wb[4*9] + 0.5f*(ymin+ymax)*wb[5*9]
               + 0.03125f*wb[6*9] + 0.03125f*wb[7*9];
        }
    }
    g_spbase[idx] = s;
}

__global__ void k_assemble() {
    int idx = blockIdx.x*256 + threadIdx.x;
    if (idx >= NB*PP*VD/4) return;
    int e = idx*4;
    int o = e & 255, p = (e >> 8) & 1023, n = e >> 18;
    int hh = p >> 5, ww = p & 31;
    int ty = (hh==0)?0:((hh==31)?2:1);
    int tx = (ww==0)?0:((ww==31)?2:1);
    float4 sp = *(const float4*)(g_spbase + (size_t)p*VD + o);
    float4 hc = *(const float4*)(g_hncon + ((size_t)(n*9 + ty*3+tx))*VD + o);
    float4 r; r.x=sp.x+hc.x; r.y=sp.y+hc.y; r.z=sp.z+hc.z; r.w=sp.w+hc.w;
    *(float4*)(g_base + (size_t)e) = r;
}

__global__ __launch_bounds__(256) void k_qh(const float* __restrict__ emb,
                                            const float* __restrict__ qw, const float* __restrict__ qb,
                                            const float* __restrict__ Wq, const float* __restrict__ bq) {
    __shared__ float es[304];
    __shared__ float qs[256];
    int n = blockIdx.x, s = blockIdx.y, c = threadIdx.x;
    for (int i=c; i<EMBD; i+=256) es[i] = emb[((size_t)n*SEQN+s)*EMBD + i];
    __syncthreads();
    float a = qb[c];
    const float* wr = qw + (size_t)c*EMBD;
    for (int e=0;e<EMBD;e++) a += es[e]*wr[e];
    qs[c] = fmaxf(a, 0.f);
    __syncthreads();
    float a2 = bq[c];
    const float* wr2 = Wq + (size_t)c*VD;
    for (int k=0;k<VD;k++) a2 += qs[k]*wr2[k];
    g_qh[((size_t)s*NB+n)*VD + c] = a2;
}

__global__ void k_repack(const float* __restrict__ w){
    int idx = blockIdx.x*256 + threadIdx.x;
    if (idx >= 9*VD*VD) return;
    int i = idx & 255;
    int o = (idx >> 8) & 255;
    int t = idx >> 16;
    g_wr[idx] = w[((size_t)o*CIN + i)*9 + t];
}

// ---------------- transposes (once each) ----------------
__global__ __launch_bounds__(256) void k_tr_in(const float* __restrict__ src, float* __restrict__ dst){
    __shared__ float t[32][33];
    int n = blockIdx.z, c0 = blockIdx.y*32, p0 = blockIdx.x*32;
    int i = threadIdx.x >> 5, j = threadIdx.x & 31;
    for (int r=0;r<32;r+=8)
        t[i+r][j] = src[((size_t)n*VD + c0+i+r)*PP + p0 + j];
    __syncthreads();
    for (int r=0;r<32;r+=8)
        dst[((size_t)n*PP + p0+i+r)*VD + c0 + j] = t[j][i+r];
}
__global__ __launch_bounds__(256) void k_tr_out(const float* __restrict__ src, float* __restrict__ dst){
    __shared__ float t[32][33];
    int n = blockIdx.z, c0 = blockIdx.y*32, p0 = blockIdx.x*32;
    int i = threadIdx.x >> 5, j = threadIdx.x & 31;
    for (int r=0;r<32;r+=8)
        t[i+r][j] = src[((size_t)n*PP + p0+i+r)*VD + c0 + j];
    __syncthreads();
    for (int r=0;r<32;r+=8)
        dst[((size_t)n*VD + c0+i+r)*PP + p0 + j] = t[j][i+r];
}

// ---------------- tf32 HMMA GEMM: C(16384x256) = A @ W^T (+fused epilogues) -------
// MODE 0: plain GEMM, K=256.   MODE 1: conv (9 shifted taps), W=g_wr, resid=base.
// EPI 0: +bias   EPI 1: +bias,relu   EPI 2: +bias,+resid,LN
// EPI 3: EPI2 + word-gate (copy fcur when inactive)   EPI 4: LN(relu(acc+resid)) (conv)
template<int MODE, int EPI>
__global__ __launch_bounds__(512, 1) void k_tc(const float* __restrict__ A, const float* __restrict__ W,
    const float* __restrict__ bias, const float* __restrict__ resid,
    const float* __restrict__ lng, const float* __restrict__ lnb,
    const int* __restrict__ words, int s, const float* __restrict__ fcur,
    float* __restrict__ C)
{
    extern __shared__ float sm[];
    const int tid  = threadIdx.x;
    const int lane = tid & 31;
    const int w    = tid >> 5;
    const int wm   = w & 3;
    const int wn   = w >> 2;
    const int tg   = lane & 3;
    const int gp   = lane >> 2;
    const int row0 = blockIdx.x*128;
    const int n    = row0 >> 10;
    const int p0   = row0 & 1023;

    float acc[2][8][4];
#pragma unroll
    for (int f=0;f<2;f++)
#pragma unroll
        for (int nf=0;nf<8;nf++)
#pragma unroll
            for (int j=0;j<4;j++) acc[f][nf][j] = 0.f;

    const int CH = MODE ? 72 : 8;

    auto ldgA = [&](int c, float4* r){
#pragma unroll
        for (int i=0;i<2;i++){
            int q = tid + i*512;
            int row = q>>3, c4 = q&7;
            if (MODE == 0){
                r[i] = *(const float4*)(A + (size_t)(row0+row)*256 + c*32 + c4*4);
            } else {
                int tap = c >> 3, kb = c & 7;
                int dh = tap/3 - 1, dw = tap%3 - 1;
                int p = p0 + row;
                int sh = (p>>5) + dh, sw = (p&31) + dw;
                float4 v = make_float4(0.f,0.f,0.f,0.f);
                if ((unsigned)sh < 32u && (unsigned)sw < 32u)
                    v = *(const float4*)(A + ((size_t)((n<<10) + (sh<<5) + sw))*256 + kb*32 + c4*4);
                r[i] = v;
            }
        }
    };
    auto ldgB = [&](int c, float4* r){
        const float* Wb; int k0;
        if (MODE == 0){ Wb = W; k0 = c*32; }
        else { Wb = g_wr + (size_t)(c>>3)*VD*VD; k0 = (c&7)*32; }
#pragma unroll
        for (int i=0;i<4;i++){
            int q = tid + i*512;
            int row = q>>3, c4 = q&7;
            r[i] = *(const float4*)(Wb + (size_t)row*256 + k0 + c4*4);
        }
    };
    auto stsA = [&](int buf, const float4* r){
        float* As = sm + buf*ASZ;
#pragma unroll
        for (int i=0;i<2;i++){
            int q = tid + i*512;
            int row = q>>3, c4 = q&7;
            float* p = As + row*PAD + c4*4;
            p[0]=tf32r(r[i].x); p[1]=tf32r(r[i].y); p[2]=tf32r(r[i].z); p[3]=tf32r(r[i].w);
        }
    };
    auto stsB = [&](int buf, const float4* r){
        float* Bs = sm + 2*ASZ + buf*BSZ;
#pragma unroll
        for (int i=0;i<4;i++){
            int q = tid + i*512;
            int row = q>>3, c4 = q&7;
            float* p = Bs + row*PAD + c4*4;
            p[0]=tf32r(r[i].x); p[1]=tf32r(r[i].y); p[2]=tf32r(r[i].z); p[3]=tf32r(r[i].w);
        }
    };
    auto compute = [&](int buf){
        const float* As = sm + buf*ASZ;
        const float* Bs = sm + 2*ASZ + buf*BSZ;
#pragma unroll
        for (int kk=0; kk<4; kk++){
            int k = kk*8;
            uint32_t af[2][4];
#pragma unroll
            for (int f=0;f<2;f++){
                int rb = wm*32 + f*16 + gp;
                af[f][0] = __float_as_uint(As[rb*PAD     + k + tg]);
                af[f][1] = __float_as_uint(As[(rb+8)*PAD + k + tg]);
                af[f][2] = __float_as_uint(As[rb*PAD     + k + tg + 4]);
                af[f][3] = __float_as_uint(As[(rb+8)*PAD + k + tg + 4]);
            }
#pragma unroll
            for (int nf=0;nf<8;nf++){
                int cb = wn*64 + nf*8 + gp;
                uint32_t bf[2];
                bf[0] = __float_as_uint(Bs[cb*PAD + k + tg]);
                bf[1] = __float_as_uint(Bs[cb*PAD + k + tg + 4]);
                mma8(acc[0][nf], af[0], bf);
                mma8(acc[1][nf], af[1], bf);
            }
        }
    };

    {
        float4 ra[2], rb[4];
        ldgA(0, ra); ldgB(0, rb);
        stsA(0, ra); stsB(0, rb);
    }
    __syncthreads();
    for (int c=0; c<CH; c++){
        float4 ra[2], rb[4];
        if (c+1 < CH){ ldgA(c+1, ra); ldgB(c+1, rb); }
        compute(c&1);
        __syncthreads();
        if (c+1 < CH){
            stsA((c+1)&1, ra); stsB((c+1)&1, rb);
            __syncthreads();
        }
    }

    // -------- epilogue --------
    if (EPI <= 1){
#pragma unroll
        for (int f=0;f<2;f++)
#pragma unroll
        for (int nf=0;nf<8;nf++){
            int colb = wn*64 + nf*8 + 2*tg;
            float2 bb = *(const float2*)(bias + colb);
#pragma unroll
            for (int h=0;h<2;h++){
                int row = row0 + wm*32 + f*16 + h*8 + gp;
                float2 o;
                o.x = acc[f][nf][2*h+0] + bb.x;
                o.y = acc[f][nf][2*h+1] + bb.y;
                if (EPI == 1){ o.x = fmaxf(o.x,0.f); o.y = fmaxf(o.y,0.f); }
                *(float2*)(C + (size_t)row*256 + colb) = o;
            }
        }
        return;
    }

    if (EPI == 3){
        if (__ldg(words + s) == 0){
#pragma unroll
            for (int f=0;f<2;f++)
#pragma unroll
            for (int nf=0;nf<8;nf++){
                int colb = wn*64 + nf*8 + 2*tg;
#pragma unroll
                for (int h=0;h<2;h++){
                    int row = row0 + wm*32 + f*16 + h*8 + gp;
                    *(float2*)(C + (size_t)row*256 + colb) =
                        *(const float2*)(fcur + (size_t)row*256 + colb);
                }
            }
            return;
        }
    }

#pragma unroll
    for (int f=0;f<2;f++)
#pragma unroll
    for (int nf=0;nf<8;nf++){
        int colb = wn*64 + nf*8 + 2*tg;
        float2 bb = make_float2(0.f, 0.f);
        if (EPI != 4) bb = *(const float2*)(bias + colb);
#pragma unroll
        for (int h=0;h<2;h++){
            int row = row0 + wm*32 + f*16 + h*8 + gp;
            float2 rr = *(const float2*)(resid + (size_t)row*256 + colb);
            float vx = acc[f][nf][2*h+0] + bb.x + rr.x;
            float vy = acc[f][nf][2*h+1] + bb.y + rr.y;
            if (EPI == 4){ vx = fmaxf(vx, 0.f); vy = fmaxf(vy, 0.f); }
            acc[f][nf][2*h+0] = vx;
            acc[f][nf][2*h+1] = vy;
        }
    }
    float2* red = (float2*)sm;   // reuse SMEM: [wn][128]
#pragma unroll
    for (int f=0;f<2;f++)
#pragma unroll
    for (int h=0;h<2;h++){
        float su = 0.f, sq = 0.f;
#pragma unroll
        for (int nf=0;nf<8;nf++){
            float vx = acc[f][nf][2*h+0], vy = acc[f][nf][2*h+1];
            su += vx + vy;
            sq += vx*vx + vy*vy;
        }
        su += __shfl_xor_sync(0xffffffffu, su, 1);
        sq += __shfl_xor_sync(0xffffffffu, sq, 1);
        su += __shfl_xor_sync(0xffffffffu, su, 2);
        sq += __shfl_xor_sync(0xffffffffu, sq, 2);
        if (tg == 0){
            int rloc = wm*32 + f*16 + h*8 + gp;
            red[wn*128 + rloc] = make_float2(su, sq);
        }
    }
    __syncthreads();
#pragma unroll
    for (int f=0;f<2;f++)
#pragma unroll
    for (int h=0;h<2;h++){
        int rloc = wm*32 + f*16 + h*8 + gp;
        float S = 0.f, Q = 0.f;
#pragma unroll
        for (int w4=0;w4<4;w4++){
            float2 v = red[w4*128 + rloc];
            S += v.x; Q += v.y;
        }
        float m  = S*(1.f/256.f);
        float rs = rsqrtf(Q*(1.f/256.f) - m*m + 1e-5f);
        int row = row0 + rloc;
#pragma unroll
        for (int nf=0;nf<8;nf++){
            int colb = wn*64 + nf*8 + 2*tg;
            float2 g2 = *(const float2*)(lng + colb);
            float2 b2 = *(const float2*)(lnb + colb);
            float2 o;
            o.x = (acc[f][nf][2*h+0]-m)*rs*g2.x + b2.x;
            o.y = (acc[f][nf][2*h+1]-m)*rs*g2.y + b2.y;
            *(float2*)(C + (size_t)row*256 + colb) = o;
        }
    }
}

// ---------------- attention (validated) ----------------
__global__ __launch_bounds__(256) void k_attn(int s) {
    __shared__ float ks[16*257];
    __shared__ float vs[16*257];
    __shared__ float sc[512];
    int p = blockIdx.x, tid = threadIdx.x;
    for (int idx=tid; idx<16*256; idx+=256) {
        int m = idx >> 8, c = idx & 255;
        ks[m*257+c] = g_kh[((size_t)(m*PP + p))*VD + c];
        vs[m*257+c] = g_vv[((size_t)(m*PP + p))*VD + c];
    }
    __syncthreads();
    const float scale = 0.08838834764831845f;
#pragma unroll
    for (int rep=0; rep<2; rep++) {
        int si = tid + rep*256;
        int h = si >> 8, l = (si >> 4) & 15, m = si & 15;
        const float* qp = g_qh + ((size_t)(s*NB + l))*VD + h*DHD;
        const float* kp = ks + m*257 + h*DHD;
        float d = 0.f;
#pragma unroll 8
        for (int k=0;k<DHD;k++) d += qp[k]*kp[k];
        sc[si] = d*scale;
    }
    __syncthreads();
    if (tid < 32) {
        float* r = sc + tid*16;
        float mx = r[0];
#pragma unroll
        for (int m=1;m<16;m++) mx = fmaxf(mx, r[m]);
        float su=0.f;
#pragma unroll
        for (int m=0;m<16;m++){ float e = __expf(r[m]-mx); r[m]=e; su+=e; }
        float inv = 1.f/su;
#pragma unroll
        for (int m=0;m<16;m++) r[m]*=inv;
    }
    __syncthreads();
    for (int idx=tid; idx<4096; idx+=256) {
        int l = idx >> 8, c = idx & 255;
        int h = c >> 7;
        const float* a = sc + (h*16+l)*16;
        float accv = 0.f;
#pragma unroll
        for (int m=0;m<16;m++) accv += a[m]*vs[m*257+c];
        g_o[((size_t)(l*PP+p))*VD + c] = accv;
    }
}

// ---------------- launch ----------------
extern "C" void kernel_launch(void* const* d_in, const int* in_sizes, int n_in,
                              void* d_out, int out_size) {
    const float* hn         = (const float*)d_in[1];
    const float* feature    = (const float*)d_in[2];
    const float* embedding  = (const float*)d_in[3];
    const int*   words      = (const int*)  d_in[4];
    const float* qconv_w    = (const float*)d_in[5];
    const float* qconv_b    = (const float*)d_in[6];
    const float* mconv_w    = (const float*)d_in[7];
    const float* mnorm_g    = (const float*)d_in[8];
    const float* mnorm_b    = (const float*)d_in[9];
    const float* in_proj_w  = (const float*)d_in[10];
    const float* in_proj_b  = (const float*)d_in[11];
    const float* out_proj_w = (const float*)d_in[12];
    const float* out_proj_b = (const float*)d_in[13];
    const float* norm_g     = (const float*)d_in[14];
    const float* norm_b     = (const float*)d_in[15];
    const float* lin1_w     = (const float*)d_in[16];
    const float* lin1_b     = (const float*)d_in[17];
    const float* lin2_w     = (const float*)d_in[18];
    const float* lin2_b     = (const float*)d_in[19];
    const float* normf_g    = (const float*)d_in[20];
    const float* normf_b    = (const float*)d_in[21];

    cudaFuncSetAttribute(k_tc<0,0>, cudaFuncAttributeMaxDynamicSharedMemorySize, SMEM_BYTES);
    cudaFuncSetAttribute(k_tc<0,1>, cudaFuncAttributeMaxDynamicSharedMemorySize, SMEM_BYTES);
    cudaFuncSetAttribute(k_tc<0,2>, cudaFuncAttributeMaxDynamicSharedMemorySize, SMEM_BYTES);
    cudaFuncSetAttribute(k_tc<0,3>, cudaFuncAttributeMaxDynamicSharedMemorySize, SMEM_BYTES);
    cudaFuncSetAttribute(k_tc<1,4>, cudaFuncAttributeMaxDynamicSharedMemorySize, SMEM_BYTES);

    float *fA, *fB, *p_t, *p_kh, *p_vv, *p_o, *p_fea1, *p_base;
    cudaGetSymbolAddress((void**)&fA,     g_featA);
    cudaGetSymbolAddress((void**)&fB,     g_featB);
    cudaGetSymbolAddress((void**)&p_t,    g_t);
    cudaGetSymbolAddress((void**)&p_kh,   g_kh);
    cudaGetSymbolAddress((void**)&p_vv,   g_vv);
    cudaGetSymbolAddress((void**)&p_o,    g_o);
    cudaGetSymbolAddress((void**)&p_fea1, g_fea1);
    cudaGetSymbolAddress((void**)&p_base, g_base);

    // one-time precompute
    k_wsum9   <<<(9*HND*VD+255)/256, 256>>>(mconv_w);
    k_spbase  <<<(PP*VD+255)/256,    256>>>(mconv_w);
    k_hncon   <<<(NB*9*VD+255)/256,  256>>>(hn);
    k_assemble<<<(NB*PP*VD/4+255)/256, 256>>>();
    k_qh      <<<dim3(NB,SEQN), 256>>>(embedding, qconv_w, qconv_b, in_proj_w, in_proj_b);
    k_repack  <<<(9*VD*VD+255)/256,  256>>>(mconv_w);
    k_tr_in   <<<dim3(32,8,NB), 256>>>(feature, fA);

    for (int s=0; s<SEQN; s++) {
        const float* fin = (s&1) ? fB : fA;
        float* fout      = (s&1) ? fA : fB;

        // conv: LN(relu(conv + base)) -> g_t
        k_tc<1,4><<<128,512,SMEM_BYTES>>>(fin, nullptr, nullptr, p_base,
                                          mnorm_g, mnorm_b, nullptr, 0, nullptr, p_t);
        k_tc<0,0><<<128,512,SMEM_BYTES>>>(p_t, in_proj_w + VD*VD,   in_proj_b + VD,
                                          nullptr, nullptr, nullptr, nullptr, 0, nullptr, p_kh);
        k_tc<0,0><<<128,512,SMEM_BYTES>>>(p_t, in_proj_w + 2*VD*VD, in_proj_b + 2*VD,
                                          nullptr, nullptr, nullptr, nullptr, 0, nullptr, p_vv);
        k_attn <<<PP,256>>>(s);
        k_tc<0,2><<<128,512,SMEM_BYTES>>>(p_o, out_proj_w, out_proj_b,
                                          p_t, norm_g, norm_b, nullptr, 0, nullptr, p_fea1);
        k_tc<0,1><<<128,512,SMEM_BYTES>>>(p_fea1, lin1_w, lin1_b,
                                          nullptr, nullptr, nullptr, nullptr, 0, nullptr, p_kh);
        k_tc<0,3><<<128,512,SMEM_BYTES>>>(p_kh, lin2_w, lin2_b,
                                          p_fea1, normf_g, normf_b, words, s, fin, fout);
    }
    k_tr_out<<<dim3(32,8,NB), 256>>>(fA, (float*)d_out);
}

// round 5
// speedup vs baseline: 5.6770x; 1.4777x over previous
#include <cuda_runtime.h>
#include <cuda_fp16.h>
#include <math.h>
#include <stdint.h>

#define NB   16
#define SEQN 20
#define PP   1024
#define VD   256
#define HND  512
#define EMBD 300
#define CIN  776
#define DHD  128

// half tiles, PADH = 40 halves/row (80B). A: 128x40x2B, B: 256x40x2B, double buffered.
#define A_BYTES 10240
#define B_BYTES 20480
#define OFF_A0  0
#define OFF_A1  10240
#define OFF_B0  20480
#define OFF_B1  40960
#define SMEM_BYTES 61440

// ---------------- scratch (device globals; no allocation) ----------------
__device__ float g_base [NB*PP*VD];
__device__ float g_t    [NB*PP*VD];
__device__ float g_kh   [NB*PP*VD];
__device__ float g_vv   [NB*PP*VD];
__device__ float g_o    [NB*PP*VD];
__device__ float g_fea1 [NB*PP*VD];
__device__ float g_featA[NB*PP*VD];   // NHWC ping
__device__ float g_featB[NB*PP*VD];   // NHWC pong
__device__ float g_wsum9[9*HND*VD];
__device__ float g_hncon[NB*9*VD];
__device__ float g_spbase[PP*VD];
__device__ float g_qh   [SEQN*NB*VD];
__device__ float g_wr   [9*VD*VD];    // [tap][oc][ic]

// ---------------- helpers ----------------
__device__ __forceinline__ uint32_t h2u(__half2 h){ return *(uint32_t*)&h; }
__device__ __forceinline__ void mma16(float* d, const uint32_t* a, const uint32_t* b){
    asm volatile("mma.sync.aligned.m16n8k16.row.col.f32.f16.f16.f32 "
        "{%0,%1,%2,%3}, {%4,%5,%6,%7}, {%8,%9}, {%0,%1,%2,%3};"
        : "+f"(d[0]), "+f"(d[1]), "+f"(d[2]), "+f"(d[3])
        : "r"(a[0]), "r"(a[1]), "r"(a[2]), "r"(a[3]), "r"(b[0]), "r"(b[1]));
}

// ---------------- precompute kernels (validated) ----------------
__global__ void k_wsum9(const float* __restrict__ w) {
    int idx = blockIdx.x*256 + threadIdx.x;
    if (idx >= 9*HND*VD) return;
    int o = idx & 255;
    int i = (idx >> 8) & 511;
    int t = idx >> 17;
    int ty = t/3, tx = t%3;
    int kh0 = (ty==0)?1:0, kh1 = (ty==2)?1:2;
    int kw0 = (tx==0)?1:0, kw1 = (tx==2)?1:2;
    const float* wb = w + ((size_t)o*CIN + 264 + i)*9;
    float s = 0.f;
    for (int kh=kh0; kh<=kh1; kh++)
        for (int kw=kw0; kw<=kw1; kw++)
            s += wb[kh*3+kw];
    g_wsum9[idx] = s;
}

__global__ void k_hncon(const float* __restrict__ hn) {
    int idx = blockIdx.x*256 + threadIdx.x;
    if (idx >= NB*9*VD) return;
    int o = idx & 255, t = (idx >> 8) % 9, n = idx / (9*256);
    const float* hp = hn + (size_t)n*HND;
    const float* wp = g_wsum9 + (size_t)t*HND*VD + o;
    float s = 0.f;
    for (int i=0;i<HND;i++) s += hp[i]*wp[(size_t)i*VD];
    g_hncon[idx] = s;
}

__global__ void k_spbase(const float* __restrict__ w) {
    int idx = blockIdx.x*256 + threadIdx.x;
    if (idx >= PP*VD) return;
    int o = idx & 255, p = idx >> 8;
    int hh = p >> 5, ww = p & 31;
    float s = 0.f;
    for (int kh=0;kh<3;kh++) {
        int gh = hh+kh-1; if ((unsigned)gh >= 32u) continue;
        for (int kw=0;kw<3;kw++) {
            int gw = ww+kw-1; if ((unsigned)gw >= 32u) continue;
            float xmin = gw*0.0625f - 1.f;
            float ymin = gh*0.0625f - 1.f;
            float xmax = xmin + 0.0625f;
            float ymax = ymin + 0.0625f;
            const float* wb = w + ((size_t)o*CIN + 256)*9 + kh*3+kw;
            s += xmin*wb[0*9] + ymin*wb[1*9] + xmax*wb[2*9] + ymax*wb[3*9]
               + 0.5f*(xmin+xmax)*wb[4*9] + 0.5f*(ymin+ymax)*wb[5*9]
               + 0.03125f*wb[6*9] + 0.03125f*wb[7*9];
        }
    }
    g_spbase[idx] = s;
}

__global__ void k_assemble() {
    int idx = blockIdx.x*256 + threadIdx.x;
    if (idx >= NB*PP*VD/4) return;
    int e = idx*4;
    int o = e & 255, p = (e >> 8) & 1023, n = e >> 18;
    int hh = p >> 5, ww = p & 31;
    int ty = (hh==0)?0:((hh==31)?2:1);
    int tx = (ww==0)?0:((ww==31)?2:1);
    float4 sp = *(const float4*)(g_spbase + (size_t)p*VD + o);
    float4 hc = *(const float4*)(g_hncon + ((size_t)(n*9 + ty*3+tx))*VD + o);
    float4 r; r.x=sp.x+hc.x; r.y=sp.y+hc.y; r.z=sp.z+hc.z; r.w=sp.w+hc.w;
    *(float4*)(g_base + (size_t)e) = r;
}

__global__ __launch_bounds__(256) void k_qh(const float* __restrict__ emb,
                                            const float* __restrict__ qw, const float* __restrict__ qb,
                                            const float* __restrict__ Wq, const float* __restrict__ bq) {
    __shared__ float es[304];
    __shared__ float qs[256];
    int n = blockIdx.x, s = blockIdx.y, c = threadIdx.x;
    for (int i=c; i<EMBD; i+=256) es[i] = emb[((size_t)n*SEQN+s)*EMBD + i];
    __syncthreads();
    float a = qb[c];
    const float* wr = qw + (size_t)c*EMBD;
    for (int e=0;e<EMBD;e++) a += es[e]*wr[e];
    qs[c] = fmaxf(a, 0.f);
    __syncthreads();
    float a2 = bq[c];
    const float* wr2 = Wq + (size_t)c*VD;
    for (int k=0;k<VD;k++) a2 += qs[k]*wr2[k];
    g_qh[((size_t)s*NB+n)*VD + c] = a2;
}

__global__ void k_repack(const float* __restrict__ w){
    int idx = blockIdx.x*256 + threadIdx.x;
    if (idx >= 9*VD*VD) return;
    int i = idx & 255;
    int o = (idx >> 8) & 255;
    int t = idx >> 16;
    g_wr[idx] = w[((size_t)o*CIN + i)*9 + t];
}

// ---------------- transposes (once each) ----------------
__global__ __launch_bounds__(256) void k_tr_in(const float* __restrict__ src, float* __restrict__ dst){
    __shared__ float t[32][33];
    int n = blockIdx.z, c0 = blockIdx.y*32, p0 = blockIdx.x*32;
    int i = threadIdx.x >> 5, j = threadIdx.x & 31;
    for (int r=0;r<32;r+=8)
        t[i+r][j] = src[((size_t)n*VD + c0+i+r)*PP + p0 + j];
    __syncthreads();
    for (int r=0;r<32;r+=8)
        dst[((size_t)n*PP + p0+i+r)*VD + c0 + j] = t[j][i+r];
}
__global__ __launch_bounds__(256) void k_tr_out(const float* __restrict__ src, float* __restrict__ dst){
    __shared__ float t[32][33];
    int n = blockIdx.z, c0 = blockIdx.y*32, p0 = blockIdx.x*32;
    int i = threadIdx.x >> 5, j = threadIdx.x & 31;
    for (int r=0;r<32;r+=8)
        t[i+r][j] = src[((size_t)n*PP + p0+i+r)*VD + c0 + j];
    __syncthreads();
    for (int r=0;r<32;r+=8)
        dst[((size_t)n*VD + c0+i+r)*PP + p0 + j] = t[j][i+r];
}

// ---------------- fp16 HMMA GEMM: C(16384x256) = A @ W^T (+fused epilogues) -------
// MODE 0: plain GEMM, K=256 (optional second weight via gridDim.y=2).
// MODE 1: conv (9 shifted taps), W=g_wr, resid=base.
// EPI 0: +bias   EPI 1: +bias,relu   EPI 2: +bias,+resid,LN
// EPI 3: EPI2 + word-gate (copy fcur when inactive)   EPI 4: LN(relu(acc+resid)) (conv)
template<int MODE, int EPI>
__global__ __launch_bounds__(512, 1) void k_tc(const float* __restrict__ A, const float* __restrict__ W,
    const float* __restrict__ bias, const float* __restrict__ resid,
    const float* __restrict__ lng, const float* __restrict__ lnb,
    const int* __restrict__ words, int s, const float* __restrict__ fcur,
    float* __restrict__ C,
    const float* __restrict__ W2, const float* __restrict__ bias2, float* __restrict__ C2)
{
    extern __shared__ char smc[];
    const int tid  = threadIdx.x;
    const int lane = tid & 31;
    const int w    = tid >> 5;
    const int wm   = w & 3;
    const int wn   = w >> 2;
    const int tg   = lane & 3;
    const int gp   = lane >> 2;
    const int row0 = blockIdx.x*128;
    const int n    = row0 >> 10;
    const int p0   = row0 & 1023;

    if (MODE == 0 && blockIdx.y == 1){ W = W2; bias = bias2; C = C2; }

    float acc[2][8][4];
#pragma unroll
    for (int f=0;f<2;f++)
#pragma unroll
        for (int nf=0;nf<8;nf++)
#pragma unroll
            for (int j=0;j<4;j++) acc[f][nf][j] = 0.f;

    const int CH = MODE ? 72 : 8;

    auto ldgA = [&](int c, float4* r){
#pragma unroll
        for (int i=0;i<2;i++){
            int q = tid + i*512;
            int row = q>>3, c4 = q&7;
            if (MODE == 0){
                r[i] = *(const float4*)(A + (size_t)(row0+row)*256 + c*32 + c4*4);
            } else {
                int tap = c >> 3, kb = c & 7;
                int dh = tap/3 - 1, dw = tap%3 - 1;
                int p = p0 + row;
                int sh = (p>>5) + dh, sw = (p&31) + dw;
                float4 v = make_float4(0.f,0.f,0.f,0.f);
                if ((unsigned)sh < 32u && (unsigned)sw < 32u)
                    v = *(const float4*)(A + ((size_t)((n<<10) + (sh<<5) + sw))*256 + kb*32 + c4*4);
                r[i] = v;
            }
        }
    };
    auto ldgB = [&](int c, float4* r){
        const float* Wb; int k0;
        if (MODE == 0){ Wb = W; k0 = c*32; }
        else { Wb = g_wr + (size_t)(c>>3)*VD*VD; k0 = (c&7)*32; }
#pragma unroll
        for (int i=0;i<4;i++){
            int q = tid + i*512;
            int row = q>>3, c4 = q&7;
            r[i] = *(const float4*)(Wb + (size_t)row*256 + k0 + c4*4);
        }
    };
    auto stsA = [&](int buf, const float4* r){
        char* As = smc + (buf ? OFF_A1 : OFF_A0);
#pragma unroll
        for (int i=0;i<2;i++){
            int q = tid + i*512;
            int row = q>>3, c4 = q&7;
            __half2 h0 = __floats2half2_rn(r[i].x, r[i].y);
            __half2 h1 = __floats2half2_rn(r[i].z, r[i].w);
            *(uint2*)(As + row*80 + c4*8) = make_uint2(h2u(h0), h2u(h1));
        }
    };
    auto stsB = [&](int buf, const float4* r){
        char* Bs = smc + (buf ? OFF_B1 : OFF_B0);
#pragma unroll
        for (int i=0;i<4;i++){
            int q = tid + i*512;
            int row = q>>3, c4 = q&7;
            __half2 h0 = __floats2half2_rn(r[i].x, r[i].y);
            __half2 h1 = __floats2half2_rn(r[i].z, r[i].w);
            *(uint2*)(Bs + row*80 + c4*8) = make_uint2(h2u(h0), h2u(h1));
        }
    };
    auto compute = [&](int buf){
        const char* As = smc + (buf ? OFF_A1 : OFF_A0);
        const char* Bs = smc + (buf ? OFF_B1 : OFF_B0);
#pragma unroll
        for (int kk=0; kk<2; kk++){
            uint32_t af[2][4];
#pragma unroll
            for (int f=0;f<2;f++){
                int rb = wm*32 + f*16 + gp;
                af[f][0] = *(const uint32_t*)(As + rb*80     + kk*32 + tg*4);
                af[f][1] = *(const uint32_t*)(As + (rb+8)*80 + kk*32 + tg*4);
                af[f][2] = *(const uint32_t*)(As + rb*80     + kk*32 + tg*4 + 16);
                af[f][3] = *(const uint32_t*)(As + (rb+8)*80 + kk*32 + tg*4 + 16);
            }
#pragma unroll
            for (int nf=0;nf<8;nf++){
                int cb = wn*64 + nf*8 + gp;
                uint32_t bf[2];
                bf[0] = *(const uint32_t*)(Bs + cb*80 + kk*32 + tg*4);
                bf[1] = *(const uint32_t*)(Bs + cb*80 + kk*32 + tg*4 + 16);
                mma16(acc[0][nf], af[0], bf);
                mma16(acc[1][nf], af[1], bf);
            }
        }
    };

    {
        float4 ra[2], rb[4];
        ldgA(0, ra); ldgB(0, rb);
        stsA(0, ra); stsB(0, rb);
    }
    __syncthreads();
    for (int c=0; c<CH; c++){
        float4 ra[2], rb[4];
        if (c+1 < CH){ ldgA(c+1, ra); ldgB(c+1, rb); }
        compute(c&1);
        __syncthreads();
        if (c+1 < CH){
            stsA((c+1)&1, ra); stsB((c+1)&1, rb);
            __syncthreads();
        }
    }

    // -------- epilogue --------
    if (EPI <= 1){
#pragma unroll
        for (int f=0;f<2;f++)
#pragma unroll
        for (int nf=0;nf<8;nf++){
            int colb = wn*64 + nf*8 + 2*tg;
            float2 bb = *(const float2*)(bias + colb);
#pragma unroll
            for (int h=0;h<2;h++){
                int row = row0 + wm*32 + f*16 + h*8 + gp;
                float2 o;
                o.x = acc[f][nf][2*h+0] + bb.x;
                o.y = acc[f][nf][2*h+1] + bb.y;
                if (EPI == 1){ o.x = fmaxf(o.x,0.f); o.y = fmaxf(o.y,0.f); }
                *(float2*)(C + (size_t)row*256 + colb) = o;
            }
        }
        return;
    }

    if (EPI == 3){
        if (__ldg(words + s) == 0){
#pragma unroll
            for (int f=0;f<2;f++)
#pragma unroll
            for (int nf=0;nf<8;nf++){
                int colb = wn*64 + nf*8 + 2*tg;
#pragma unroll
                for (int h=0;h<2;h++){
                    int row = row0 + wm*32 + f*16 + h*8 + gp;
                    *(float2*)(C + (size_t)row*256 + colb) =
                        *(const float2*)(fcur + (size_t)row*256 + colb);
                }
            }
            return;
        }
    }

#pragma unroll
    for (int f=0;f<2;f++)
#pragma unroll
    for (int nf=0;nf<8;nf++){
        int colb = wn*64 + nf*8 + 2*tg;
        float2 bb = make_float2(0.f, 0.f);
        if (EPI != 4) bb = *(const float2*)(bias + colb);
#pragma unroll
        for (int h=0;h<2;h++){
            int row = row0 + wm*32 + f*16 + h*8 + gp;
            float2 rr = *(const float2*)(resid + (size_t)row*256 + colb);
            float vx = acc[f][nf][2*h+0] + bb.x + rr.x;
            float vy = acc[f][nf][2*h+1] + bb.y + rr.y;
            if (EPI == 4){ vx = fmaxf(vx, 0.f); vy = fmaxf(vy, 0.f); }
            acc[f][nf][2*h+0] = vx;
            acc[f][nf][2*h+1] = vy;
        }
    }
    float2* red = (float2*)smc;   // reuse SMEM: [wn][128]
#pragma unroll
    for (int f=0;f<2;f++)
#pragma unroll
    for (int h=0;h<2;h++){
        float su = 0.f, sq = 0.f;
#pragma unroll
        for (int nf=0;nf<8;nf++){
            float vx = acc[f][nf][2*h+0], vy = acc[f][nf][2*h+1];
            su += vx + vy;
            sq += vx*vx + vy*vy;
        }
        su += __shfl_xor_sync(0xffffffffu, su, 1);
        sq += __shfl_xor_sync(0xffffffffu, sq, 1);
        su += __shfl_xor_sync(0xffffffffu, su, 2);
        sq += __shfl_xor_sync(0xffffffffu, sq, 2);
        if (tg == 0){
            int rloc = wm*32 + f*16 + h*8 + gp;
            red[wn*128 + rloc] = make_float2(su, sq);
        }
    }
    __syncthreads();
#pragma unroll
    for (int f=0;f<2;f++)
#pragma unroll
    for (int h=0;h<2;h++){
        int rloc = wm*32 + f*16 + h*8 + gp;
        float S = 0.f, Q = 0.f;
#pragma unroll
        for (int w4=0;w4<4;w4++){
            float2 v = red[w4*128 + rloc];
            S += v.x; Q += v.y;
        }
        float m  = S*(1.f/256.f);
        float rs = rsqrtf(Q*(1.f/256.f) - m*m + 1e-5f);
        int row = row0 + rloc;
#pragma unroll
        for (int nf=0;nf<8;nf++){
            int colb = wn*64 + nf*8 + 2*tg;
            float2 g2 = *(const float2*)(lng + colb);
            float2 b2 = *(const float2*)(lnb + colb);
            float2 o;
            o.x = (acc[f][nf][2*h+0]-m)*rs*g2.x + b2.x;
            o.y = (acc[f][nf][2*h+1]-m)*rs*g2.y + b2.y;
            *(float2*)(C + (size_t)row*256 + colb) = o;
        }
    }
}

// ---------------- attention (validated) ----------------
__global__ __launch_bounds__(256) void k_attn(int s) {
    __shared__ float ks[16*257];
    __shared__ float vs[16*257];
    __shared__ float sc[512];
    int p = blockIdx.x, tid = threadIdx.x;
    for (int idx=tid; idx<16*256; idx+=256) {
        int m = idx >> 8, c = idx & 255;
        ks[m*257+c] = g_kh[((size_t)(m*PP + p))*VD + c];
        vs[m*257+c] = g_vv[((size_t)(m*PP + p))*VD + c];
    }
    __syncthreads();
    const float scale = 0.08838834764831845f;
#pragma unroll
    for (int rep=0; rep<2; rep++) {
        int si = tid + rep*256;
        int h = si >> 8, l = (si >> 4) & 15, m = si & 15;
        const float* qp = g_qh + ((size_t)(s*NB + l))*VD + h*DHD;
        const float* kp = ks + m*257 + h*DHD;
        float d = 0.f;
#pragma unroll 8
        for (int k=0;k<DHD;k++) d += qp[k]*kp[k];
        sc[si] = d*scale;
    }
    __syncthreads();
    if (tid < 32) {
        float* r = sc + tid*16;
        float mx = r[0];
#pragma unroll
        for (int m=1;m<16;m++) mx = fmaxf(mx, r[m]);
        float su=0.f;
#pragma unroll
        for (int m=0;m<16;m++){ float e = __expf(r[m]-mx); r[m]=e; su+=e; }
        float inv = 1.f/su;
#pragma unroll
        for (int m=0;m<16;m++) r[m]*=inv;
    }
    __syncthreads();
    for (int idx=tid; idx<4096; idx+=256) {
        int l = idx >> 8, c = idx & 255;
        int h = c >> 7;
        const float* a = sc + (h*16+l)*16;
        float accv = 0.f;
#pragma unroll
        for (int m=0;m<16;m++) accv += a[m]*vs[m*257+c];
        g_o[((size_t)(l*PP+p))*VD + c] = accv;
    }
}

// ---------------- launch ----------------
extern "C" void kernel_launch(void* const* d_in, const int* in_sizes, int n_in,
                              void* d_out, int out_size) {
    const float* hn         = (const float*)d_in[1];
    const float* feature    = (const float*)d_in[2];
    const float* embedding  = (const float*)d_in[3];
    const int*   words      = (const int*)  d_in[4];
    const float* qconv_w    = (const float*)d_in[5];
    const float* qconv_b    = (const float*)d_in[6];
    const float* mconv_w    = (const float*)d_in[7];
    const float* mnorm_g    = (const float*)d_in[8];
    const float* mnorm_b    = (const float*)d_in[9];
    const float* in_proj_w  = (const float*)d_in[10];
    const float* in_proj_b  = (const float*)d_in[11];
    const float* out_proj_w = (const float*)d_in[12];
    const float* out_proj_b = (const float*)d_in[13];
    const float* norm_g     = (const float*)d_in[14];
    const float* norm_b     = (const float*)d_in[15];
    const float* lin1_w     = (const float*)d_in[16];
    const float* lin1_b     = (const float*)d_in[17];
    const float* lin2_w     = (const float*)d_in[18];
    const float* lin2_b     = (const float*)d_in[19];
    const float* normf_g    = (const float*)d_in[20];
    const float* normf_b    = (const float*)d_in[21];

    cudaFuncSetAttribute(k_tc<0,0>, cudaFuncAttributeMaxDynamicSharedMemorySize, SMEM_BYTES);
    cudaFuncSetAttribute(k_tc<0,1>, cudaFuncAttributeMaxDynamicSharedMemorySize, SMEM_BYTES);
    cudaFuncSetAttribute(k_tc<0,2>, cudaFuncAttributeMaxDynamicSharedMemorySize, SMEM_BYTES);
    cudaFuncSetAttribute(k_tc<0,3>, cudaFuncAttributeMaxDynamicSharedMemorySize, SMEM_BYTES);
    cudaFuncSetAttribute(k_tc<1,4>, cudaFuncAttributeMaxDynamicSharedMemorySize, SMEM_BYTES);

    float *fA, *fB, *p_t, *p_kh, *p_vv, *p_o, *p_fea1, *p_base;
    cudaGetSymbolAddress((void**)&fA,     g_featA);
    cudaGetSymbolAddress((void**)&fB,     g_featB);
    cudaGetSymbolAddress((void**)&p_t,    g_t);
    cudaGetSymbolAddress((void**)&p_kh,   g_kh);
    cudaGetSymbolAddress((void**)&p_vv,   g_vv);
    cudaGetSymbolAddress((void**)&p_o,    g_o);
    cudaGetSymbolAddress((void**)&p_fea1, g_fea1);
    cudaGetSymbolAddress((void**)&p_base, g_base);

    // one-time precompute
    k_wsum9   <<<(9*HND*VD+255)/256, 256>>>(mconv_w);
    k_spbase  <<<(PP*VD+255)/256,    256>>>(mconv_w);
    k_hncon   <<<(NB*9*VD+255)/256,  256>>>(hn);
    k_assemble<<<(NB*PP*VD/4+255)/256, 256>>>();
    k_qh      <<<dim3(NB,SEQN), 256>>>(embedding, qconv_w, qconv_b, in_proj_w, in_proj_b);
    k_repack  <<<(9*VD*VD+255)/256,  256>>>(mconv_w);
    k_tr_in   <<<dim3(32,8,NB), 256>>>(feature, fA);

    for (int s=0; s<SEQN; s++) {
        const float* fin = (s&1) ? fB : fA;
        float* fout      = (s&1) ? fA : fB;

        // conv: LN(relu(conv + base)) -> g_t
        k_tc<1,4><<<128,512,SMEM_BYTES>>>(fin, nullptr, nullptr, p_base,
                                          mnorm_g, mnorm_b, nullptr, 0, nullptr, p_t,
                                          nullptr, nullptr, nullptr);
        // K and V projections merged: grid.y=0 -> kh, grid.y=1 -> vv
        k_tc<0,0><<<dim3(128,2),512,SMEM_BYTES>>>(p_t, in_proj_w + VD*VD, in_proj_b + VD,
                                          nullptr, nullptr, nullptr, nullptr, 0, nullptr, p_kh,
                                          in_proj_w + 2*VD*VD, in_proj_b + 2*VD, p_vv);
        k_attn <<<PP,256>>>(s);
        k_tc<0,2><<<128,512,SMEM_BYTES>>>(p_o, out_proj_w, out_proj_b,
                                          p_t, norm_g, norm_b, nullptr, 0, nullptr, p_fea1,
                                          nullptr, nullptr, nullptr);
        k_tc<0,1><<<128,512,SMEM_BYTES>>>(p_fea1, lin1_w, lin1_b,
                                          nullptr, nullptr, nullptr, nullptr, 0, nullptr, p_kh,
                                          nullptr, nullptr, nullptr);
        k_tc<0,3><<<128,512,SMEM_BYTES>>>(p_kh, lin2_w, lin2_b,
                                          p_fea1, normf_g, normf_b, words, s, fin, fout,
                                          nullptr, nullptr, nullptr);
    }
    k_tr_out<<<dim3(32,8,NB), 256>>>(fA, (float*)d_out);
}

// round 6
// speedup vs baseline: 5.6799x; 1.0005x over previous
#include <cuda_runtime.h>
#include <cuda_fp16.h>
#include <math.h>
#include <stdint.h>

#define NB   16
#define SEQN 20
#define PP   1024
#define VD   256
#define HND  512
#define EMBD 300
#define CIN  776
#define DHD  128

// half tiles, PADH = 40 halves/row (80B). A: 128x40x2B, B: 256x40x2B, double buffered.
#define A_BYTES 10240
#define B_BYTES 20480
#define OFF_A0  0
#define OFF_A1  10240
#define OFF_B0  20480
#define OFF_B1  40960
#define SMEM_BYTES 61440

// ---------------- scratch (device globals; no allocation) ----------------
__device__ float g_base [NB*PP*VD];
__device__ float g_t    [NB*PP*VD];
__device__ float g_kh   [NB*PP*VD];
__device__ float g_vv   [NB*PP*VD];
__device__ float g_o    [NB*PP*VD];
__device__ float g_fea1 [NB*PP*VD];
__device__ float g_featA[NB*PP*VD];   // NHWC ping
__device__ float g_featB[NB*PP*VD];   // NHWC pong
__device__ float g_wsum9[9*HND*VD];
__device__ float g_hncon[NB*9*VD];
__device__ float g_spbase[PP*VD];
__device__ float g_qh   [SEQN*NB*VD];
__device__ float g_wr   [9*VD*VD];    // [tap][oc][ic]

// ---------------- helpers ----------------
__device__ __forceinline__ uint32_t h2u(__half2 h){ return *(uint32_t*)&h; }
__device__ __forceinline__ void mma16(float* d, const uint32_t* a, const uint32_t* b){
    asm volatile("mma.sync.aligned.m16n8k16.row.col.f32.f16.f16.f32 "
        "{%0,%1,%2,%3}, {%4,%5,%6,%7}, {%8,%9}, {%0,%1,%2,%3};"
        : "+f"(d[0]), "+f"(d[1]), "+f"(d[2]), "+f"(d[3])
        : "r"(a[0]), "r"(a[1]), "r"(a[2]), "r"(a[3]), "r"(b[0]), "r"(b[1]));
}

// ---------------- precompute kernels (validated) ----------------
__global__ void k_wsum9(const float* __restrict__ w) {
    int idx = blockIdx.x*256 + threadIdx.x;
    if (idx >= 9*HND*VD) return;
    int o = idx & 255;
    int i = (idx >> 8) & 511;
    int t = idx >> 17;
    int ty = t/3, tx = t%3;
    int kh0 = (ty==0)?1:0, kh1 = (ty==2)?1:2;
    int kw0 = (tx==0)?1:0, kw1 = (tx==2)?1:2;
    const float* wb = w + ((size_t)o*CIN + 264 + i)*9;
    float s = 0.f;
    for (int kh=kh0; kh<=kh1; kh++)
        for (int kw=kw0; kw<=kw1; kw++)
            s += wb[kh*3+kw];
    g_wsum9[idx] = s;
}

__global__ void k_hncon(const float* __restrict__ hn) {
    int idx = blockIdx.x*256 + threadIdx.x;
    if (idx >= NB*9*VD) return;
    int o = idx & 255, t = (idx >> 8) % 9, n = idx / (9*256);
    const float* hp = hn + (size_t)n*HND;
    const float* wp = g_wsum9 + (size_t)t*HND*VD + o;
    float s = 0.f;
    for (int i=0;i<HND;i++) s += hp[i]*wp[(size_t)i*VD];
    g_hncon[idx] = s;
}

__global__ void k_spbase(const float* __restrict__ w) {
    int idx = blockIdx.x*256 + threadIdx.x;
    if (idx >= PP*VD) return;
    int o = idx & 255, p = idx >> 8;
    int hh = p >> 5, ww = p & 31;
    float s = 0.f;
    for (int kh=0;kh<3;kh++) {
        int gh = hh+kh-1; if ((unsigned)gh >= 32u) continue;
        for (int kw=0;kw<3;kw++) {
            int gw = ww+kw-1; if ((unsigned)gw >= 32u) continue;
            float xmin = gw*0.0625f - 1.f;
            float ymin = gh*0.0625f - 1.f;
            float xmax = xmin + 0.0625f;
            float ymax = ymin + 0.0625f;
            const float* wb = w + ((size_t)o*CIN + 256)*9 + kh*3+kw;
            s += xmin*wb[0*9] + ymin*wb[1*9] + xmax*wb[2*9] + ymax*wb[3*9]
               + 0.5f*(xmin+xmax)*wb[4*9] + 0.5f*(ymin+ymax)*wb[5*9]
               + 0.03125f*wb[6*9] + 0.03125f*wb[7*9];
        }
    }
    g_spbase[idx] = s;
}

__global__ void k_assemble() {
    int idx = blockIdx.x*256 + threadIdx.x;
    if (idx >= NB*PP*VD/4) return;
    int e = idx*4;
    int o = e & 255, p = (e >> 8) & 1023, n = e >> 18;
    int hh = p >> 5, ww = p & 31;
    int ty = (hh==0)?0:((hh==31)?2:1);
    int tx = (ww==0)?0:((ww==31)?2:1);
    float4 sp = *(const float4*)(g_spbase + (size_t)p*VD + o);
    float4 hc = *(const float4*)(g_hncon + ((size_t)(n*9 + ty*3+tx))*VD + o);
    float4 r; r.x=sp.x+hc.x; r.y=sp.y+hc.y; r.z=sp.z+hc.z; r.w=sp.w+hc.w;
    *(float4*)(g_base + (size_t)e) = r;
}

__global__ __launch_bounds__(256) void k_qh(const float* __restrict__ emb,
                                            const float* __restrict__ qw, const float* __restrict__ qb,
                                            const float* __restrict__ Wq, const float* __restrict__ bq) {
    __shared__ float es[304];
    __shared__ float qs[256];
    int n = blockIdx.x, s = blockIdx.y, c = threadIdx.x;
    for (int i=c; i<EMBD; i+=256) es[i] = emb[((size_t)n*SEQN+s)*EMBD + i];
    __syncthreads();
    float a = qb[c];
    const float* wr = qw + (size_t)c*EMBD;
    for (int e=0;e<EMBD;e++) a += es[e]*wr[e];
    qs[c] = fmaxf(a, 0.f);
    __syncthreads();
    float a2 = bq[c];
    const float* wr2 = Wq + (size_t)c*VD;
    for (int k=0;k<VD;k++) a2 += qs[k]*wr2[k];
    g_qh[((size_t)s*NB+n)*VD + c] = a2;
}

__global__ void k_repack(const float* __restrict__ w){
    int idx = blockIdx.x*256 + threadIdx.x;
    if (idx >= 9*VD*VD) return;
    int i = idx & 255;
    int o = (idx >> 8) & 255;
    int t = idx >> 16;
    g_wr[idx] = w[((size_t)o*CIN + i)*9 + t];
}

// ---------------- transposes (once each) ----------------
__global__ __launch_bounds__(256) void k_tr_in(const float* __restrict__ src, float* __restrict__ dst){
    __shared__ float t[32][33];
    int n = blockIdx.z, c0 = blockIdx.y*32, p0 = blockIdx.x*32;
    int i = threadIdx.x >> 5, j = threadIdx.x & 31;
    for (int r=0;r<32;r+=8)
        t[i+r][j] = src[((size_t)n*VD + c0+i+r)*PP + p0 + j];
    __syncthreads();
    for (int r=0;r<32;r+=8)
        dst[((size_t)n*PP + p0+i+r)*VD + c0 + j] = t[j][i+r];
}
__global__ __launch_bounds__(256) void k_tr_out(const float* __restrict__ src, float* __restrict__ dst){
    __shared__ float t[32][33];
    int n = blockIdx.z, c0 = blockIdx.y*32, p0 = blockIdx.x*32;
    int i = threadIdx.x >> 5, j = threadIdx.x & 31;
    for (int r=0;r<32;r+=8)
        t[i+r][j] = src[((size_t)n*PP + p0+i+r)*VD + c0 + j];
    __syncthreads();
    for (int r=0;r<32;r+=8)
        dst[((size_t)n*VD + c0+i+r)*PP + p0 + j] = t[j][i+r];
}

// ---------------- fp16 HMMA GEMM: C(16384x256) = A @ W^T (+fused epilogues) -------
// MODE 0: plain GEMM, K=256 (optional second weight via gridDim.y=2).
// MODE 1: conv (9 shifted taps), W=g_wr, resid=base.
// EPI 0: +bias   EPI 1: +bias,relu   EPI 2: +bias,+resid,LN
// EPI 3: EPI2 + word-gate (copy fcur when inactive)   EPI 4: LN(relu(acc+resid)) (conv)
template<int MODE, int EPI>
__global__ __launch_bounds__(512, 1) void k_tc(const float* __restrict__ A, const float* __restrict__ W,
    const float* __restrict__ bias, const float* __restrict__ resid,
    const float* __restrict__ lng, const float* __restrict__ lnb,
    const int* __restrict__ words, int s, const float* __restrict__ fcur,
    float* __restrict__ C,
    const float* __restrict__ W2, const float* __restrict__ bias2, float* __restrict__ C2)
{
    extern __shared__ char smc[];
    const int tid  = threadIdx.x;
    const int lane = tid & 31;
    const int w    = tid >> 5;
    const int wm   = w & 3;
    const int wn   = w >> 2;
    const int tg   = lane & 3;
    const int gp   = lane >> 2;
    const int row0 = blockIdx.x*128;
    const int n    = row0 >> 10;
    const int p0   = row0 & 1023;

    if (MODE == 0 && blockIdx.y == 1){ W = W2; bias = bias2; C = C2; }

    float acc[2][8][4];
#pragma unroll
    for (int f=0;f<2;f++)
#pragma unroll
        for (int nf=0;nf<8;nf++)
#pragma unroll
            for (int j=0;j<4;j++) acc[f][nf][j] = 0.f;

    const int CH = MODE ? 72 : 8;

    auto ldgA = [&](int c, float4* r){
#pragma unroll
        for (int i=0;i<2;i++){
            int q = tid + i*512;
            int row = q>>3, c4 = q&7;
            if (MODE == 0){
                r[i] = *(const float4*)(A + (size_t)(row0+row)*256 + c*32 + c4*4);
            } else {
                int tap = c >> 3, kb = c & 7;
                int dh = tap/3 - 1, dw = tap%3 - 1;
                int p = p0 + row;
                int sh = (p>>5) + dh, sw = (p&31) + dw;
                float4 v = make_float4(0.f,0.f,0.f,0.f);
                if ((unsigned)sh < 32u && (unsigned)sw < 32u)
                    v = *(const float4*)(A + ((size_t)((n<<10) + (sh<<5) + sw))*256 + kb*32 + c4*4);
                r[i] = v;
            }
        }
    };
    auto ldgB = [&](int c, float4* r){
        const float* Wb; int k0;
        if (MODE == 0){ Wb = W; k0 = c*32; }
        else { Wb = g_wr + (size_t)(c>>3)*VD*VD; k0 = (c&7)*32; }
#pragma unroll
        for (int i=0;i<4;i++){
            int q = tid + i*512;
            int row = q>>3, c4 = q&7;
            r[i] = *(const float4*)(Wb + (size_t)row*256 + k0 + c4*4);
        }
    };
    auto stsA = [&](int buf, const float4* r){
        char* As = smc + (buf ? OFF_A1 : OFF_A0);
#pragma unroll
        for (int i=0;i<2;i++){
            int q = tid + i*512;
            int row = q>>3, c4 = q&7;
            __half2 h0 = __floats2half2_rn(r[i].x, r[i].y);
            __half2 h1 = __floats2half2_rn(r[i].z, r[i].w);
            *(uint2*)(As + row*80 + c4*8) = make_uint2(h2u(h0), h2u(h1));
        }
    };
    auto stsB = [&](int buf, const float4* r){
        char* Bs = smc + (buf ? OFF_B1 : OFF_B0);
#pragma unroll
        for (int i=0;i<4;i++){
            int q = tid + i*512;
            int row = q>>3, c4 = q&7;
            __half2 h0 = __floats2half2_rn(r[i].x, r[i].y);
            __half2 h1 = __floats2half2_rn(r[i].z, r[i].w);
            *(uint2*)(Bs + row*80 + c4*8) = make_uint2(h2u(h0), h2u(h1));
        }
    };
    auto compute = [&](int buf){
        const char* As = smc + (buf ? OFF_A1 : OFF_A0);
        const char* Bs = smc + (buf ? OFF_B1 : OFF_B0);
#pragma unroll
        for (int kk=0; kk<2; kk++){
            uint32_t af[2][4];
#pragma unroll
            for (int f=0;f<2;f++){
                int rb = wm*32 + f*16 + gp;
                af[f][0] = *(const uint32_t*)(As + rb*80     + kk*32 + tg*4);
                af[f][1] = *(const uint32_t*)(As + (rb+8)*80 + kk*32 + tg*4);
                af[f][2] = *(const uint32_t*)(As + rb*80     + kk*32 + tg*4 + 16);
                af[f][3] = *(const uint32_t*)(As + (rb+8)*80 + kk*32 + tg*4 + 16);
            }
#pragma unroll
            for (int nf=0;nf<8;nf++){
                int cb = wn*64 + nf*8 + gp;
                uint32_t bf[2];
                bf[0] = *(const uint32_t*)(Bs + cb*80 + kk*32 + tg*4);
                bf[1] = *(const uint32_t*)(Bs + cb*80 + kk*32 + tg*4 + 16);
                mma16(acc[0][nf], af[0], bf);
                mma16(acc[1][nf], af[1], bf);
            }
        }
    };

    {
        float4 ra[2], rb[4];
        ldgA(0, ra); ldgB(0, rb);
        stsA(0, ra); stsB(0, rb);
    }
    __syncthreads();
    for (int c=0; c<CH; c++){
        float4 ra[2], rb[4];
        if (c+1 < CH){ ldgA(c+1, ra); ldgB(c+1, rb); }
        compute(c&1);
        __syncthreads();
        if (c+1 < CH){
            stsA((c+1)&1, ra); stsB((c+1)&1, rb);
            __syncthreads();
        }
    }

    // -------- epilogue --------
    if (EPI <= 1){
#pragma unroll
        for (int f=0;f<2;f++)
#pragma unroll
        for (int nf=0;nf<8;nf++){
            int colb = wn*64 + nf*8 + 2*tg;
            float2 bb = *(const float2*)(bias + colb);
#pragma unroll
            for (int h=0;h<2;h++){
                int row = row0 + wm*32 + f*16 + h*8 + gp;
                float2 o;
                o.x = acc[f][nf][2*h+0] + bb.x;
                o.y = acc[f][nf][2*h+1] + bb.y;
                if (EPI == 1){ o.x = fmaxf(o.x,0.f); o.y = fmaxf(o.y,0.f); }
                *(float2*)(C + (size_t)row*256 + colb) = o;
            }
        }
        return;
    }

    if (EPI == 3){
        if (__ldg(words + s) == 0){
#pragma unroll
            for (int f=0;f<2;f++)
#pragma unroll
            for (int nf=0;nf<8;nf++){
                int colb = wn*64 + nf*8 + 2*tg;
#pragma unroll
                for (int h=0;h<2;h++){
                    int row = row0 + wm*32 + f*16 + h*8 + gp;
                    *(float2*)(C + (size_t)row*256 + colb) =
                        *(const float2*)(fcur + (size_t)row*256 + colb);
                }
            }
            return;
        }
    }

#pragma unroll
    for (int f=0;f<2;f++)
#pragma unroll
    for (int nf=0;nf<8;nf++){
        int colb = wn*64 + nf*8 + 2*tg;
        float2 bb = make_float2(0.f, 0.f);
        if (EPI != 4) bb = *(const float2*)(bias + colb);
#pragma unroll
        for (int h=0;h<2;h++){
            int row = row0 + wm*32 + f*16 + h*8 + gp;
            float2 rr = *(const float2*)(resid + (size_t)row*256 + colb);
            float vx = acc[f][nf][2*h+0] + bb.x + rr.x;
            float vy = acc[f][nf][2*h+1] + bb.y + rr.y;
            if (EPI == 4){ vx = fmaxf(vx, 0.f); vy = fmaxf(vy, 0.f); }
            acc[f][nf][2*h+0] = vx;
            acc[f][nf][2*h+1] = vy;
        }
    }
    float2* red = (float2*)smc;   // reuse SMEM: [wn][128]
#pragma unroll
    for (int f=0;f<2;f++)
#pragma unroll
    for (int h=0;h<2;h++){
        float su = 0.f, sq = 0.f;
#pragma unroll
        for (int nf=0;nf<8;nf++){
            float vx = acc[f][nf][2*h+0], vy = acc[f][nf][2*h+1];
            su += vx + vy;
            sq += vx*vx + vy*vy;
        }
        su += __shfl_xor_sync(0xffffffffu, su, 1);
        sq += __shfl_xor_sync(0xffffffffu, sq, 1);
        su += __shfl_xor_sync(0xffffffffu, su, 2);
        sq += __shfl_xor_sync(0xffffffffu, sq, 2);
        if (tg == 0){
            int rloc = wm*32 + f*16 + h*8 + gp;
            red[wn*128 + rloc] = make_float2(su, sq);
        }
    }
    __syncthreads();
#pragma unroll
    for (int f=0;f<2;f++)
#pragma unroll
    for (int h=0;h<2;h++){
        int rloc = wm*32 + f*16 + h*8 + gp;
        float S = 0.f, Q = 0.f;
#pragma unroll
        for (int w4=0;w4<4;w4++){
            float2 v = red[w4*128 + rloc];
            S += v.x; Q += v.y;
        }
        float m  = S*(1.f/256.f);
        float rs = rsqrtf(Q*(1.f/256.f) - m*m + 1e-5f);
        int row = row0 + rloc;
#pragma unroll
        for (int nf=0;nf<8;nf++){
            int colb = wn*64 + nf*8 + 2*tg;
            float2 g2 = *(const float2*)(lng + colb);
            float2 b2 = *(const float2*)(lnb + colb);
            float2 o;
            o.x = (acc[f][nf][2*h+0]-m)*rs*g2.x + b2.x;
            o.y = (acc[f][nf][2*h+1]-m)*rs*g2.y + b2.y;
            *(float2*)(C + (size_t)row*256 + colb) = o;
        }
    }
}

// ---------------- attention (validated) ----------------
__global__ __launch_bounds__(256) void k_attn(int s) {
    __shared__ float ks[16*257];
    __shared__ float vs[16*257];
    __shared__ float sc[512];
    int p = blockIdx.x, tid = threadIdx.x;
    for (int idx=tid; idx<16*256; idx+=256) {
        int m = idx >> 8, c = idx & 255;
        ks[m*257+c] = g_kh[((size_t)(m*PP + p))*VD + c];
        vs[m*257+c] = g_vv[((size_t)(m*PP + p))*VD + c];
    }
    __syncthreads();
    const float scale = 0.08838834764831845f;
#pragma unroll
    for (int rep=0; rep<2; rep++) {
        int si = tid + rep*256;
        int h = si >> 8, l = (si >> 4) & 15, m = si & 15;
        const float* qp = g_qh + ((size_t)(s*NB + l))*VD + h*DHD;
        const float* kp = ks + m*257 + h*DHD;
        float d = 0.f;
#pragma unroll 8
        for (int k=0;k<DHD;k++) d += qp[k]*kp[k];
        sc[si] = d*scale;
    }
    __syncthreads();
    if (tid < 32) {
        float* r = sc + tid*16;
        float mx = r[0];
#pragma unroll
        for (int m=1;m<16;m++) mx = fmaxf(mx, r[m]);
        float su=0.f;
#pragma unroll
        for (int m=0;m<16;m++){ float e = __expf(r[m]-mx); r[m]=e; su+=e; }
        float inv = 1.f/su;
#pragma unroll
        for (int m=0;m<16;m++) r[m]*=inv;
    }
    __syncthreads();
    for (int idx=tid; idx<4096; idx+=256) {
        int l = idx >> 8, c = idx & 255;
        int h = c >> 7;
        const float* a = sc + (h*16+l)*16;
        float accv = 0.f;
#pragma unroll
        for (int m=0;m<16;m++) accv += a[m]*vs[m*257+c];
        g_o[((size_t)(l*PP+p))*VD + c] = accv;
    }
}

// ---------------- launch ----------------
extern "C" void kernel_launch(void* const* d_in, const int* in_sizes, int n_in,
                              void* d_out, int out_size) {
    const float* hn         = (const float*)d_in[1];
    const float* feature    = (const float*)d_in[2];
    const float* embedding  = (const float*)d_in[3];
    const int*   words      = (const int*)  d_in[4];
    const float* qconv_w    = (const float*)d_in[5];
    const float* qconv_b    = (const float*)d_in[6];
    const float* mconv_w    = (const float*)d_in[7];
    const float* mnorm_g    = (const float*)d_in[8];
    const float* mnorm_b    = (const float*)d_in[9];
    const float* in_proj_w  = (const float*)d_in[10];
    const float* in_proj_b  = (const float*)d_in[11];
    const float* out_proj_w = (const float*)d_in[12];
    const float* out_proj_b = (const float*)d_in[13];
    const float* norm_g     = (const float*)d_in[14];
    const float* norm_b     = (const float*)d_in[15];
    const float* lin1_w     = (const float*)d_in[16];
    const float* lin1_b     = (const float*)d_in[17];
    const float* lin2_w     = (const float*)d_in[18];
    const float* lin2_b     = (const float*)d_in[19];
    const float* normf_g    = (const float*)d_in[20];
    const float* normf_b    = (const float*)d_in[21];

    cudaFuncSetAttribute(k_tc<0,0>, cudaFuncAttributeMaxDynamicSharedMemorySize, SMEM_BYTES);
    cudaFuncSetAttribute(k_tc<0,1>, cudaFuncAttributeMaxDynamicSharedMemorySize, SMEM_BYTES);
    cudaFuncSetAttribute(k_tc<0,2>, cudaFuncAttributeMaxDynamicSharedMemorySize, SMEM_BYTES);
    cudaFuncSetAttribute(k_tc<0,3>, cudaFuncAttributeMaxDynamicSharedMemorySize, SMEM_BYTES);
    cudaFuncSetAttribute(k_tc<1,4>, cudaFuncAttributeMaxDynamicSharedMemorySize, SMEM_BYTES);

    float *fA, *fB, *p_t, *p_kh, *p_vv, *p_o, *p_fea1, *p_base;
    cudaGetSymbolAddress((void**)&fA,     g_featA);
    cudaGetSymbolAddress((void**)&fB,     g_featB);
    cudaGetSymbolAddress((void**)&p_t,    g_t);
    cudaGetSymbolAddress((void**)&p_kh,   g_kh);
    cudaGetSymbolAddress((void**)&p_vv,   g_vv);
    cudaGetSymbolAddress((void**)&p_o,    g_o);
    cudaGetSymbolAddress((void**)&p_fea1, g_fea1);
    cudaGetSymbolAddress((void**)&p_base, g_base);

    // one-time precompute
    k_wsum9   <<<(9*HND*VD+255)/256, 256>>>(mconv_w);
    k_spbase  <<<(PP*VD+255)/256,    256>>>(mconv_w);
    k_hncon   <<<(NB*9*VD+255)/256,  256>>>(hn);
    k_assemble<<<(NB*PP*VD/4+255)/256, 256>>>();
    k_qh      <<<dim3(NB,SEQN), 256>>>(embedding, qconv_w, qconv_b, in_proj_w, in_proj_b);
    k_repack  <<<(9*VD*VD+255)/256,  256>>>(mconv_w);
    k_tr_in   <<<dim3(32,8,NB), 256>>>(feature, fA);

    for (int s=0; s<SEQN; s++) {
        const float* fin = (s&1) ? fB : fA;
        float* fout      = (s&1) ? fA : fB;

        // conv: LN(relu(conv + base)) -> g_t
        k_tc<1,4><<<128,512,SMEM_BYTES>>>(fin, nullptr, nullptr, p_base,
                                          mnorm_g, mnorm_b, nullptr, 0, nullptr, p_t,
                                          nullptr, nullptr, nullptr);
        // K and V projections merged: grid.y=0 -> kh, grid.y=1 -> vv
        k_tc<0,0><<<dim3(128,2),512,SMEM_BYTES>>>(p_t, in_proj_w + VD*VD, in_proj_b + VD,
                                          nullptr, nullptr, nullptr, nullptr, 0, nullptr, p_kh,
                                          in_proj_w + 2*VD*VD, in_proj_b + 2*VD, p_vv);
        k_attn <<<PP,256>>>(s);
        k_tc<0,2><<<128,512,SMEM_BYTES>>>(p_o, out_proj_w, out_proj_b,
                                          p_t, norm_g, norm_b, nullptr, 0, nullptr, p_fea1,
                                          nullptr, nullptr, nullptr);
        k_tc<0,1><<<128,512,SMEM_BYTES>>>(p_fea1, lin1_w, lin1_b,
                                          nullptr, nullptr, nullptr, nullptr, 0, nullptr, p_kh,
                                          nullptr, nullptr, nullptr);
        k_tc<0,3><<<128,512,SMEM_BYTES>>>(p_kh, lin2_w, lin2_b,
                                          p_fea1, normf_g, normf_b, words, s, fin, fout,
                                          nullptr, nullptr, nullptr);
    }
    k_tr_out<<<dim3(32,8,NB), 256>>>(fA, (float*)d_out);
}